// round 4
// baseline (speedup 1.0000x reference)
#include <cuda_runtime.h>
#include <cuda_bf16.h>

// CholeskyMMNet: fused MLP (32->512->512->512->512->528) + per-row L@L^T.
// One CTA = 64 rows, 512 threads, activations resident in shared memory.
//
// Inputs (metadata order):
//  0: q     [65536,32]  f32
//  1: W_in  [32,512]    2: b_in [512]
//  3: W_h1  [512,512]   4: b_h1 [512]
//  5: W_h2  [512,512]   6: b_h2 [512]
//  7: W_out [512,512]   8: b_out[512]
//  9: W_o   [512,528]  10: b_o  [528]
// Output: M [65536,32,32] f32

#define TM 64          // rows per CTA
#define NT 512         // threads per CTA
#define KC 16          // k-chunk for streamed weight tiles
#define HDIM 512
#define NTRIL_COLS 528
#define QDIM 32
#define BIAS_F 2.0f

// shared layout (floats):
//  xs : [0, 32768)            64x512 activations
//  ws : [32768, 49152)        16384 floats (64KB) weight tile buffer
//  qs : [49152, 51200)        64x32 q tile
//  ps : [0, 33792)            64x528 L_params overlay (valid only after last GEMM)
#define SMEM_FLOATS (32768 + 16384 + 2048)
#define SMEM_BYTES  (SMEM_FLOATS * 4)

// Generic 512->512 layer: y = f(x @ W + b) (+ x), x in smem, W streamed.
template<bool RELU, bool RES>
__device__ __forceinline__ void layer512(float* __restrict__ xs,
                                         float* __restrict__ ws,
                                         const float* __restrict__ W,
                                         const float* __restrict__ b,
                                         int rowg, int colg, int tid)
{
    float acc[8][8];
    #pragma unroll
    for (int i = 0; i < 8; i++)
        #pragma unroll
        for (int j = 0; j < 8; j++) acc[i][j] = 0.f;

    for (int kt = 0; kt < HDIM; kt += KC) {
        // load W[kt..kt+16)[0..512) : 2048 float4, 4 per thread
        const float4* wg = (const float4*)(W + (size_t)kt * HDIM);
        float4* wsv = (float4*)ws;
        #pragma unroll
        for (int i = 0; i < 4; i++) wsv[tid + i * NT] = wg[tid + i * NT];
        __syncthreads();

        #pragma unroll
        for (int kk = 0; kk < KC; kk++) {
            float a[8], bb[8];
            #pragma unroll
            for (int i = 0; i < 8; i++) a[i] = xs[(rowg * 8 + i) * HDIM + kt + kk];
            #pragma unroll
            for (int j = 0; j < 8; j++) bb[j] = ws[kk * HDIM + colg + 64 * j];
            #pragma unroll
            for (int i = 0; i < 8; i++)
                #pragma unroll
                for (int j = 0; j < 8; j++) acc[i][j] = fmaf(a[i], bb[j], acc[i][j]);
        }
        __syncthreads();   // protects ws reload and (final iter) xs overwrite
    }

    #pragma unroll
    for (int j = 0; j < 8; j++) {
        int c = colg + 64 * j;
        float bv = __ldg(b + c);
        #pragma unroll
        for (int i = 0; i < 8; i++) {
            int r = rowg * 8 + i;
            float v = acc[i][j] + bv;
            if (RELU) v = fmaxf(v, 0.f);
            if (RES)  v += xs[r * HDIM + c];
            xs[r * HDIM + c] = v;
        }
    }
    __syncthreads();
}

__global__ void __launch_bounds__(NT)
cholesky_mmnet_kernel(const float* __restrict__ q,
                      const float* __restrict__ Win,  const float* __restrict__ bin,
                      const float* __restrict__ Wh1,  const float* __restrict__ bh1,
                      const float* __restrict__ Wh2,  const float* __restrict__ bh2,
                      const float* __restrict__ Wout, const float* __restrict__ bout,
                      const float* __restrict__ Wo,   const float* __restrict__ bo,
                      float* __restrict__ out)
{
    extern __shared__ float s[];
    float* xs = s;                  // [64][512]
    float* ws = s + 32768;          // [16384]
    float* qs = s + 32768 + 16384;  // [64][32]
    float* ps = s;                  // [64][528] overlay

    const int tid  = threadIdx.x;
    const int rowg = tid >> 6;      // 0..7
    const int colg = tid & 63;      // 0..63
    const int row0 = blockIdx.x * TM;

    // ---- load q tile (64x32 = 512 float4) ----
    {
        const float4* qg = (const float4*)(q + (size_t)row0 * QDIM);
        ((float4*)qs)[tid] = qg[tid];
    }

    // ---- layer 0: x = relu(q @ W_in + b_in), k = 32, W_in fully in ws ----
    {
        const float4* wg = (const float4*)Win;   // 4096 float4
        float4* wsv = (float4*)ws;
        #pragma unroll
        for (int i = 0; i < 8; i++) wsv[tid + i * NT] = wg[tid + i * NT];
        __syncthreads();

        float acc[8][8];
        #pragma unroll
        for (int i = 0; i < 8; i++)
            #pragma unroll
            for (int j = 0; j < 8; j++) acc[i][j] = 0.f;

        #pragma unroll
        for (int kk = 0; kk < QDIM; kk++) {
            float a[8], bb[8];
            #pragma unroll
            for (int i = 0; i < 8; i++) a[i] = qs[(rowg * 8 + i) * QDIM + kk];
            #pragma unroll
            for (int j = 0; j < 8; j++) bb[j] = ws[kk * HDIM + colg + 64 * j];
            #pragma unroll
            for (int i = 0; i < 8; i++)
                #pragma unroll
                for (int j = 0; j < 8; j++) acc[i][j] = fmaf(a[i], bb[j], acc[i][j]);
        }

        #pragma unroll
        for (int j = 0; j < 8; j++) {
            int c = colg + 64 * j;
            float bv = __ldg(bin + c);
            #pragma unroll
            for (int i = 0; i < 8; i++) {
                float v = fmaxf(acc[i][j] + bv, 0.f);
                xs[(rowg * 8 + i) * HDIM + c] = v;
            }
        }
        __syncthreads();
    }

    // ---- hidden layers with residual ----
    layer512<true, true>(xs, ws, Wh1, bh1, rowg, colg, tid);
    layer512<true, true>(xs, ws, Wh2, bh2, rowg, colg, tid);
    // ---- embed = x @ W_out + b_out (no relu, no residual) ----
    layer512<false, false>(xs, ws, Wout, bout, rowg, colg, tid);

    // ---- L_params = embed @ W_o + b_o  (cols = 528) ----
    {
        float acc[8][9];
        #pragma unroll
        for (int i = 0; i < 8; i++)
            #pragma unroll
            for (int j = 0; j < 9; j++) acc[i][j] = 0.f;

        const bool has9 = (colg < 16);   // col 512 + colg valid only for colg<16

        for (int kt = 0; kt < HDIM; kt += KC) {
            // load W_o[kt..kt+16)[0..528): 2112 float4
            const float4* wg = (const float4*)(Wo + (size_t)kt * NTRIL_COLS);
            float4* wsv = (float4*)ws;
            for (int i = tid; i < (KC * NTRIL_COLS) / 4; i += NT) wsv[i] = wg[i];
            __syncthreads();

            #pragma unroll
            for (int kk = 0; kk < KC; kk++) {
                float a[8], bb[9];
                #pragma unroll
                for (int i = 0; i < 8; i++) a[i] = xs[(rowg * 8 + i) * HDIM + kt + kk];
                #pragma unroll
                for (int j = 0; j < 8; j++) bb[j] = ws[kk * NTRIL_COLS + colg + 64 * j];
                bb[8] = has9 ? ws[kk * NTRIL_COLS + 512 + colg] : 0.f;
                #pragma unroll
                for (int i = 0; i < 8; i++)
                    #pragma unroll
                    for (int j = 0; j < 9; j++) acc[i][j] = fmaf(a[i], bb[j], acc[i][j]);
            }
            __syncthreads();   // all xs/ws reads done before overlay writes below
        }

        // write L_params into overlay ps [64][528] (overwrites xs — safe post-sync)
        #pragma unroll
        for (int j = 0; j < 8; j++) {
            int c = colg + 64 * j;
            float bv = __ldg(bo + c);
            #pragma unroll
            for (int i = 0; i < 8; i++)
                ps[(rowg * 8 + i) * NTRIL_COLS + c] = acc[i][j] + bv;
        }
        if (has9) {
            int c = 512 + colg;
            float bv = __ldg(bo + c);
            #pragma unroll
            for (int i = 0; i < 8; i++)
                ps[(rowg * 8 + i) * NTRIL_COLS + c] = acc[i][8] + bv;
        }
        __syncthreads();
    }

    // ---- M = L @ L^T per row ----
    // L[i][k] = ps[32 + i*(i-1)/2 + k] (k<i), ps[i]+BIAS (k==i), 0 (k>i)
    for (int idx = tid; idx < TM * QDIM * QDIM; idx += NT) {
        int r  = idx >> 10;
        int ij = idx & 1023;
        int i  = ij >> 5;
        int j  = ij & 31;
        const float* pr = ps + r * NTRIL_COLS;

        int mn = i < j ? i : j;
        int mx = i < j ? j : i;
        int bi = 32 + (i * (i - 1)) / 2;
        int bj = 32 + (j * (j - 1)) / 2;

        float sum = 0.f;
        for (int k = 0; k < mn; k++)
            sum = fmaf(pr[bi + k], pr[bj + k], sum);

        if (i == j) {
            float d = pr[i] + BIAS_F;
            sum = fmaf(d, d, sum);
        } else {
            // L[mx][mn] (strict lower) * (diag of mn)
            float lml = pr[32 + (mx * (mx - 1)) / 2 + mn];
            sum = fmaf(lml, pr[mn] + BIAS_F, sum);
        }
        out[(size_t)(row0 + r) * 1024 + ij] = sum;
    }
}

extern "C" void kernel_launch(void* const* d_in, const int* in_sizes, int n_in,
                              void* d_out, int out_size)
{
    const float* q    = (const float*)d_in[0];
    const float* Win  = (const float*)d_in[1];
    const float* bin  = (const float*)d_in[2];
    const float* Wh1  = (const float*)d_in[3];
    const float* bh1  = (const float*)d_in[4];
    const float* Wh2  = (const float*)d_in[5];
    const float* bh2  = (const float*)d_in[6];
    const float* Wout = (const float*)d_in[7];
    const float* bout = (const float*)d_in[8];
    const float* Wo   = (const float*)d_in[9];
    const float* bo   = (const float*)d_in[10];
    float* out = (float*)d_out;

    const int B = in_sizes[0] / QDIM;       // 65536
    const int grid = B / TM;                // 1024

    cudaFuncSetAttribute(cholesky_mmnet_kernel,
                         cudaFuncAttributeMaxDynamicSharedMemorySize, SMEM_BYTES);
    cholesky_mmnet_kernel<<<grid, NT, SMEM_BYTES>>>(
        q, Win, bin, Wh1, bh1, Wh2, bh2, Wout, bout, Wo, bo, out);
}

// round 5
// speedup vs baseline: 1.0001x; 1.0001x over previous
#include <cuda_runtime.h>
#include <cuda_bf16.h>

// CholeskyMMNet: fused MLP (32->512->512->512->512->528) + per-row L@L^T.
// One CTA = 64 rows, 512 threads, activations resident in shared memory.
//
// Inputs (metadata order):
//  0: q     [65536,32]  f32
//  1: W_in  [32,512]    2: b_in [512]
//  3: W_h1  [512,512]   4: b_h1 [512]
//  5: W_h2  [512,512]   6: b_h2 [512]
//  7: W_out [512,512]   8: b_out[512]
//  9: W_o   [512,528]  10: b_o  [528]
// Output: M [65536,32,32] f32

#define TM 64          // rows per CTA
#define NT 512         // threads per CTA
#define KC 16          // k-chunk for streamed weight tiles
#define HDIM 512
#define NTRIL_COLS 528
#define QDIM 32
#define BIAS_F 2.0f

// shared layout (floats):
//  xs : [0, 32768)            64x512 activations
//  ws : [32768, 49152)        16384 floats (64KB) weight tile buffer
//  qs : [49152, 51200)        64x32 q tile
//  ps : [0, 33792)            64x528 L_params overlay (valid only after last GEMM)
#define SMEM_FLOATS (32768 + 16384 + 2048)
#define SMEM_BYTES  (SMEM_FLOATS * 4)

// Generic 512->512 layer: y = f(x @ W + b) (+ x), x in smem, W streamed.
template<bool RELU, bool RES>
__device__ __forceinline__ void layer512(float* __restrict__ xs,
                                         float* __restrict__ ws,
                                         const float* __restrict__ W,
                                         const float* __restrict__ b,
                                         int rowg, int colg, int tid)
{
    float acc[8][8];
    #pragma unroll
    for (int i = 0; i < 8; i++)
        #pragma unroll
        for (int j = 0; j < 8; j++) acc[i][j] = 0.f;

    for (int kt = 0; kt < HDIM; kt += KC) {
        // load W[kt..kt+16)[0..512) : 2048 float4, 4 per thread
        const float4* wg = (const float4*)(W + (size_t)kt * HDIM);
        float4* wsv = (float4*)ws;
        #pragma unroll
        for (int i = 0; i < 4; i++) wsv[tid + i * NT] = wg[tid + i * NT];
        __syncthreads();

        #pragma unroll
        for (int kk = 0; kk < KC; kk++) {
            float a[8], bb[8];
            #pragma unroll
            for (int i = 0; i < 8; i++) a[i] = xs[(rowg * 8 + i) * HDIM + kt + kk];
            #pragma unroll
            for (int j = 0; j < 8; j++) bb[j] = ws[kk * HDIM + colg + 64 * j];
            #pragma unroll
            for (int i = 0; i < 8; i++)
                #pragma unroll
                for (int j = 0; j < 8; j++) acc[i][j] = fmaf(a[i], bb[j], acc[i][j]);
        }
        __syncthreads();   // protects ws reload and (final iter) xs overwrite
    }

    #pragma unroll
    for (int j = 0; j < 8; j++) {
        int c = colg + 64 * j;
        float bv = __ldg(b + c);
        #pragma unroll
        for (int i = 0; i < 8; i++) {
            int r = rowg * 8 + i;
            float v = acc[i][j] + bv;
            if (RELU) v = fmaxf(v, 0.f);
            if (RES)  v += xs[r * HDIM + c];
            xs[r * HDIM + c] = v;
        }
    }
    __syncthreads();
}

__global__ void __launch_bounds__(NT)
cholesky_mmnet_kernel(const float* __restrict__ q,
                      const float* __restrict__ Win,  const float* __restrict__ bin,
                      const float* __restrict__ Wh1,  const float* __restrict__ bh1,
                      const float* __restrict__ Wh2,  const float* __restrict__ bh2,
                      const float* __restrict__ Wout, const float* __restrict__ bout,
                      const float* __restrict__ Wo,   const float* __restrict__ bo,
                      float* __restrict__ out)
{
    extern __shared__ float s[];
    float* xs = s;                  // [64][512]
    float* ws = s + 32768;          // [16384]
    float* qs = s + 32768 + 16384;  // [64][32]
    float* ps = s;                  // [64][528] overlay

    const int tid  = threadIdx.x;
    const int rowg = tid >> 6;      // 0..7
    const int colg = tid & 63;      // 0..63
    const int row0 = blockIdx.x * TM;

    // ---- load q tile (64x32 = 512 float4) ----
    {
        const float4* qg = (const float4*)(q + (size_t)row0 * QDIM);
        ((float4*)qs)[tid] = qg[tid];
    }

    // ---- layer 0: x = relu(q @ W_in + b_in), k = 32, W_in fully in ws ----
    {
        const float4* wg = (const float4*)Win;   // 4096 float4
        float4* wsv = (float4*)ws;
        #pragma unroll
        for (int i = 0; i < 8; i++) wsv[tid + i * NT] = wg[tid + i * NT];
        __syncthreads();

        float acc[8][8];
        #pragma unroll
        for (int i = 0; i < 8; i++)
            #pragma unroll
            for (int j = 0; j < 8; j++) acc[i][j] = 0.f;

        #pragma unroll
        for (int kk = 0; kk < QDIM; kk++) {
            float a[8], bb[8];
            #pragma unroll
            for (int i = 0; i < 8; i++) a[i] = qs[(rowg * 8 + i) * QDIM + kk];
            #pragma unroll
            for (int j = 0; j < 8; j++) bb[j] = ws[kk * HDIM + colg + 64 * j];
            #pragma unroll
            for (int i = 0; i < 8; i++)
                #pragma unroll
                for (int j = 0; j < 8; j++) acc[i][j] = fmaf(a[i], bb[j], acc[i][j]);
        }

        #pragma unroll
        for (int j = 0; j < 8; j++) {
            int c = colg + 64 * j;
            float bv = __ldg(bin + c);
            #pragma unroll
            for (int i = 0; i < 8; i++) {
                float v = fmaxf(acc[i][j] + bv, 0.f);
                xs[(rowg * 8 + i) * HDIM + c] = v;
            }
        }
        __syncthreads();
    }

    // ---- hidden layers with residual ----
    layer512<true, true>(xs, ws, Wh1, bh1, rowg, colg, tid);
    layer512<true, true>(xs, ws, Wh2, bh2, rowg, colg, tid);
    // ---- embed = x @ W_out + b_out (no relu, no residual) ----
    layer512<false, false>(xs, ws, Wout, bout, rowg, colg, tid);

    // ---- L_params = embed @ W_o + b_o  (cols = 528) ----
    {
        float acc[8][9];
        #pragma unroll
        for (int i = 0; i < 8; i++)
            #pragma unroll
            for (int j = 0; j < 9; j++) acc[i][j] = 0.f;

        const bool has9 = (colg < 16);   // col 512 + colg valid only for colg<16

        for (int kt = 0; kt < HDIM; kt += KC) {
            // load W_o[kt..kt+16)[0..528): 2112 float4
            const float4* wg = (const float4*)(Wo + (size_t)kt * NTRIL_COLS);
            float4* wsv = (float4*)ws;
            for (int i = tid; i < (KC * NTRIL_COLS) / 4; i += NT) wsv[i] = wg[i];
            __syncthreads();

            #pragma unroll
            for (int kk = 0; kk < KC; kk++) {
                float a[8], bb[9];
                #pragma unroll
                for (int i = 0; i < 8; i++) a[i] = xs[(rowg * 8 + i) * HDIM + kt + kk];
                #pragma unroll
                for (int j = 0; j < 8; j++) bb[j] = ws[kk * NTRIL_COLS + colg + 64 * j];
                bb[8] = has9 ? ws[kk * NTRIL_COLS + 512 + colg] : 0.f;
                #pragma unroll
                for (int i = 0; i < 8; i++)
                    #pragma unroll
                    for (int j = 0; j < 9; j++) acc[i][j] = fmaf(a[i], bb[j], acc[i][j]);
            }
            __syncthreads();   // all xs/ws reads done before overlay writes below
        }

        // write L_params into overlay ps [64][528] (overwrites xs — safe post-sync)
        #pragma unroll
        for (int j = 0; j < 8; j++) {
            int c = colg + 64 * j;
            float bv = __ldg(bo + c);
            #pragma unroll
            for (int i = 0; i < 8; i++)
                ps[(rowg * 8 + i) * NTRIL_COLS + c] = acc[i][j] + bv;
        }
        if (has9) {
            int c = 512 + colg;
            float bv = __ldg(bo + c);
            #pragma unroll
            for (int i = 0; i < 8; i++)
                ps[(rowg * 8 + i) * NTRIL_COLS + c] = acc[i][8] + bv;
        }
        __syncthreads();
    }

    // ---- M = L @ L^T per row ----
    // L[i][k] = ps[32 + i*(i-1)/2 + k] (k<i), ps[i]+BIAS (k==i), 0 (k>i)
    for (int idx = tid; idx < TM * QDIM * QDIM; idx += NT) {
        int r  = idx >> 10;
        int ij = idx & 1023;
        int i  = ij >> 5;
        int j  = ij & 31;
        const float* pr = ps + r * NTRIL_COLS;

        int mn = i < j ? i : j;
        int mx = i < j ? j : i;
        int bi = 32 + (i * (i - 1)) / 2;
        int bj = 32 + (j * (j - 1)) / 2;

        float sum = 0.f;
        for (int k = 0; k < mn; k++)
            sum = fmaf(pr[bi + k], pr[bj + k], sum);

        if (i == j) {
            float d = pr[i] + BIAS_F;
            sum = fmaf(d, d, sum);
        } else {
            // L[mx][mn] (strict lower) * (diag of mn)
            float lml = pr[32 + (mx * (mx - 1)) / 2 + mn];
            sum = fmaf(lml, pr[mn] + BIAS_F, sum);
        }
        out[(size_t)(row0 + r) * 1024 + ij] = sum;
    }
}

extern "C" void kernel_launch(void* const* d_in, const int* in_sizes, int n_in,
                              void* d_out, int out_size)
{
    const float* q    = (const float*)d_in[0];
    const float* Win  = (const float*)d_in[1];
    const float* bin  = (const float*)d_in[2];
    const float* Wh1  = (const float*)d_in[3];
    const float* bh1  = (const float*)d_in[4];
    const float* Wh2  = (const float*)d_in[5];
    const float* bh2  = (const float*)d_in[6];
    const float* Wout = (const float*)d_in[7];
    const float* bout = (const float*)d_in[8];
    const float* Wo   = (const float*)d_in[9];
    const float* bo   = (const float*)d_in[10];
    float* out = (float*)d_out;

    const int B = in_sizes[0] / QDIM;       // 65536
    const int grid = B / TM;                // 1024

    cudaFuncSetAttribute(cholesky_mmnet_kernel,
                         cudaFuncAttributeMaxDynamicSharedMemorySize, SMEM_BYTES);
    cholesky_mmnet_kernel<<<grid, NT, SMEM_BYTES>>>(
        q, Win, bin, Wh1, bh1, Wh2, bh2, Wout, bout, Wo, bo, out);
}

// round 7
// speedup vs baseline: 1.3258x; 1.3257x over previous
#include <cuda_runtime.h>
#include <cuda_bf16.h>
#include <cstdint>

// CholeskyMMNet via mma.sync (bf16 hi/lo split, fp32 accum) — no sm_103a-only PTX.
// prep_kernel: transpose+split weights -> __device__ bf16 [n][k].
// main_kernel: 64 rows/CTA fused MLP (activations smem-resident) + L@L^T.

#define QDIM 32
#define HDIM 512
#define NTRIL 528
#define BIAS_F 2.0f

__device__ __nv_bfloat16 g_Wi_h[512*64],  g_Wi_l[512*64];
__device__ __nv_bfloat16 g_W1_h[512*512], g_W1_l[512*512];
__device__ __nv_bfloat16 g_W2_h[512*512], g_W2_l[512*512];
__device__ __nv_bfloat16 g_Wu_h[512*512], g_Wu_l[512*512];
__device__ __nv_bfloat16 g_Wo_h[528*512], g_Wo_l[528*512];

// smem: xs [64 rows][2048B] (hi 1KB | lo 1KB per row, XOR-swizzled) at 0..128K
//       ws [512 n][128B]    (hi 64B | lo 64B per row, XOR-swizzled) at 128K..192K
//       Lp overlay [64][528] fp32 at 0 (valid after layer-4 epilogue)
#define WS_BASE 131072
#define SMEM_BYTES 196608
#define XS(r,k,sel)   ((r)*2048 + (((((sel)<<10) + ((k)<<1))) ^ (((r)&7)<<4)))
#define WSOFF(n,kl,sel) (WS_BASE + (n)*128 + (((((sel)<<6) + ((kl)<<1))) ^ (((n)&7)<<4)))

__device__ __forceinline__ uint32_t smem_u32(const void* p) {
    uint32_t a;
    asm("{ .reg .u64 t; cvta.to.shared.u64 t, %1; cvt.u32.u64 %0, t; }" : "=r"(a) : "l"(p));
    return a;
}

#define LDSM4(d0,d1,d2,d3, addr) \
    asm volatile("ldmatrix.sync.aligned.m8n8.x4.shared.b16 {%0,%1,%2,%3}, [%4];" \
        : "=r"(d0),"=r"(d1),"=r"(d2),"=r"(d3) : "r"(addr))

#define MMA16816(c, a0,a1,a2,a3, b0,b1) \
    asm volatile("mma.sync.aligned.m16n8k16.row.col.f32.bf16.bf16.f32 " \
        "{%0,%1,%2,%3}, {%4,%5,%6,%7}, {%8,%9}, {%0,%1,%2,%3};" \
        : "+f"((c)[0]),"+f"((c)[1]),"+f"((c)[2]),"+f"((c)[3]) \
        : "r"(a0),"r"(a1),"r"(a2),"r"(a3), "r"(b0),"r"(b1))

__device__ __forceinline__ void split2(float a, float b, uint32_t& h, uint32_t& l) {
    __nv_bfloat16 ha = __float2bfloat16(a), hb = __float2bfloat16(b);
    __nv_bfloat162 hp = __halves2bfloat162(ha, hb);
    __nv_bfloat162 lp = __halves2bfloat162(
        __float2bfloat16(a - __bfloat162float(ha)),
        __float2bfloat16(b - __bfloat162float(hb)));
    h = *(uint32_t*)&hp; l = *(uint32_t*)&lp;
}
__device__ __forceinline__ float rd2(const char* sm, int off0, int off1, int idx) {
    // reconstruct fp32 = hi + lo for element idx (0/1) of a bf162 pair
    __nv_bfloat162 h = *(const __nv_bfloat162*)(sm + off0);
    __nv_bfloat162 l = *(const __nv_bfloat162*)(sm + off1);
    return idx ? (__bfloat162float(h.y) + __bfloat162float(l.y))
               : (__bfloat162float(h.x) + __bfloat162float(l.x));
}

// One GEMM layer: D[64][512] = X[64][K] @ W^T (W given [n][k] hi/lo), fused epilogue.
// TO_LP: layer-4 path — scalar tail for cols 512..527, then write fp32 L_params overlay.
template<int NCHUNK, bool RELU, bool RES, bool TO_LP>
__device__ void tc_layer(char* __restrict__ sm, uint32_t smb,
                         const __nv_bfloat16* __restrict__ Wh,
                         const __nv_bfloat16* __restrict__ Wl,
                         int Kw, const float* __restrict__ bias)
{
    const int tid  = threadIdx.x;
    const int warp = tid >> 5, lane = tid & 31;
    const int mblk = warp & 3, nblk = warp >> 2;

    float acc[16][4];
    #pragma unroll
    for (int t = 0; t < 16; t++)
        #pragma unroll
        for (int e = 0; e < 4; e++) acc[t][e] = 0.f;

    const int rA  = mblk * 16 + (lane & 15);
    const int k8  = (lane >> 4) << 3;
    const int nB0 = nblk * 128 + (lane & 15);

    for (int ch = 0; ch < NCHUNK; ch++) {
        const int kofs = ch * 32;
        // stage weight chunk [512 n][32 k] hi+lo into swizzled ws
        #pragma unroll
        for (int it = 0; it < 4; it++) {
            int i = tid + it * 512;
            int n = i >> 2, kq = i & 3;
            uint4 vh = *(const uint4*)(Wh + (size_t)n * Kw + kofs + kq * 8);
            uint4 vl = *(const uint4*)(Wl + (size_t)n * Kw + kofs + kq * 8);
            int s = (n & 7) << 4;
            *(uint4*)(sm + WS_BASE + n * 128 + (((kq << 4)     ) ^ s)) = vh;
            *(uint4*)(sm + WS_BASE + n * 128 + ((64 + (kq << 4)) ^ s)) = vl;
        }
        __syncthreads();

        #pragma unroll
        for (int ks = 0; ks < 2; ks++) {
            const int kk  = kofs + ks * 16 + k8;     // global k for A
            const int klB = ks * 16 + k8;            // chunk-local k for B
            uint32_t ah[4], al[4];
            LDSM4(ah[0], ah[1], ah[2], ah[3], smb + XS(rA, kk, 0));
            LDSM4(al[0], al[1], al[2], al[3], smb + XS(rA, kk, 1));
            #pragma unroll
            for (int n16 = 0; n16 < 8; n16++) {
                uint32_t bh[4], bl[4];
                LDSM4(bh[0], bh[1], bh[2], bh[3], smb + WSOFF(nB0 + n16 * 16, klB, 0));
                LDSM4(bl[0], bl[1], bl[2], bl[3], smb + WSOFF(nB0 + n16 * 16, klB, 1));
                float* cA = acc[n16 * 2 + 0];
                float* cB = acc[n16 * 2 + 1];
                MMA16816(cA, ah[0],ah[1],ah[2],ah[3], bh[0], bh[2]);
                MMA16816(cB, ah[0],ah[1],ah[2],ah[3], bh[1], bh[3]);
                MMA16816(cA, ah[0],ah[1],ah[2],ah[3], bl[0], bl[2]);
                MMA16816(cB, ah[0],ah[1],ah[2],ah[3], bl[1], bl[3]);
                MMA16816(cA, al[0],al[1],al[2],al[3], bh[0], bh[2]);
                MMA16816(cB, al[0],al[1],al[2],al[3], bh[1], bh[3]);
            }
        }
        __syncthreads();
    }

    float tail0 = 0.f, tail1 = 0.f;
    int tr = 0, tc = 0;
    if (TO_LP) {
        // scalar pass for W_o cols 512..527 — must read xs BEFORE Lp overlay writes
        tr = tid >> 3; tc = (tid & 7) * 2;
        const __nv_bfloat16* w0h = Wh + (size_t)(512 + tc) * 512;
        const __nv_bfloat16* w0l = Wl + (size_t)(512 + tc) * 512;
        const __nv_bfloat16* w1h = w0h + 512;
        const __nv_bfloat16* w1l = w0l + 512;
        for (int k = 0; k < 512; k += 2) {
            float x0 = rd2(sm, XS(tr, k, 0), XS(tr, k, 1), 0);
            float x1 = rd2(sm, XS(tr, k, 0), XS(tr, k, 1), 1);
            float a0 = __bfloat162float(w0h[k])   + __bfloat162float(w0l[k]);
            float a1 = __bfloat162float(w0h[k+1]) + __bfloat162float(w0l[k+1]);
            float b0 = __bfloat162float(w1h[k])   + __bfloat162float(w1l[k]);
            float b1 = __bfloat162float(w1h[k+1]) + __bfloat162float(w1l[k+1]);
            tail0 = fmaf(x0, a0, fmaf(x1, a1, tail0));
            tail1 = fmaf(x0, b0, fmaf(x1, b1, tail1));
        }
        __syncthreads();   // all xs reads complete before overlay writes
    }

    // epilogue
    #pragma unroll
    for (int t = 0; t < 16; t++) {
        const int n16 = t >> 1, s8 = t & 1;
        const int col = nblk * 128 + n16 * 16 + s8 * 8 + 2 * (lane & 3);
        const int r0  = mblk * 16 + (lane >> 2);
        const int r1  = r0 + 8;
        float b0v = __ldg(bias + col), b1v = __ldg(bias + col + 1);
        float y00 = acc[t][0] + b0v, y01 = acc[t][1] + b1v;
        float y10 = acc[t][2] + b0v, y11 = acc[t][3] + b1v;
        if (RELU) {
            y00 = fmaxf(y00, 0.f); y01 = fmaxf(y01, 0.f);
            y10 = fmaxf(y10, 0.f); y11 = fmaxf(y11, 0.f);
        }
        if (RES) {
            y00 += rd2(sm, XS(r0, col, 0), XS(r0, col, 1), 0);
            y01 += rd2(sm, XS(r0, col, 0), XS(r0, col, 1), 1);
            y10 += rd2(sm, XS(r1, col, 0), XS(r1, col, 1), 0);
            y11 += rd2(sm, XS(r1, col, 0), XS(r1, col, 1), 1);
        }
        if (TO_LP) {
            float* lp = (float*)sm;
            lp[r0 * NTRIL + col] = y00; lp[r0 * NTRIL + col + 1] = y01;
            lp[r1 * NTRIL + col] = y10; lp[r1 * NTRIL + col + 1] = y11;
        } else {
            uint32_t h, l;
            split2(y00, y01, h, l);
            *(uint32_t*)(sm + XS(r0, col, 0)) = h;
            *(uint32_t*)(sm + XS(r0, col, 1)) = l;
            split2(y10, y11, h, l);
            *(uint32_t*)(sm + XS(r1, col, 0)) = h;
            *(uint32_t*)(sm + XS(r1, col, 1)) = l;
        }
    }
    if (TO_LP) {
        float* lp = (float*)sm;
        lp[tr * NTRIL + 512 + tc]     = tail0 + __ldg(bias + 512 + tc);
        lp[tr * NTRIL + 512 + tc + 1] = tail1 + __ldg(bias + 513 + tc);
    }
    __syncthreads();
}

__global__ void __launch_bounds__(512, 1)
main_kernel(const float* __restrict__ q,
            const float* __restrict__ bin, const float* __restrict__ bh1,
            const float* __restrict__ bh2, const float* __restrict__ bout,
            const float* __restrict__ bo,  float* __restrict__ out)
{
    extern __shared__ char sm[];
    const uint32_t smb = smem_u32(sm);
    const int tid  = threadIdx.x;
    const int row0 = blockIdx.x * 64;

    // stage q (64x32 fp32) into xs hi/lo (k 0..31)
    {
        int r = tid >> 3, kq = (tid & 7) * 4;
        float4 v = *(const float4*)(q + (size_t)(row0 + r) * QDIM + kq);
        uint32_t h, l;
        split2(v.x, v.y, h, l);
        *(uint32_t*)(sm + XS(r, kq, 0)) = h;
        *(uint32_t*)(sm + XS(r, kq, 1)) = l;
        split2(v.z, v.w, h, l);
        *(uint32_t*)(sm + XS(r, kq + 2, 0)) = h;
        *(uint32_t*)(sm + XS(r, kq + 2, 1)) = l;
    }
    __syncthreads();

    tc_layer<1,  true,  false, false>(sm, smb, g_Wi_h, g_Wi_l, 64,  bin);
    tc_layer<16, true,  true,  false>(sm, smb, g_W1_h, g_W1_l, 512, bh1);
    tc_layer<16, true,  true,  false>(sm, smb, g_W2_h, g_W2_l, 512, bh2);
    tc_layer<16, false, false, false>(sm, smb, g_Wu_h, g_Wu_l, 512, bout);
    tc_layer<16, false, false, true >(sm, smb, g_Wo_h, g_Wo_l, 512, bo);

    // M = L @ L^T from Lp overlay (fp32, verified path)
    const float* ps = (const float*)sm;
    for (int idx = tid; idx < 64 * QDIM * QDIM; idx += 512) {
        int r = idx >> 10, ij = idx & 1023, i = ij >> 5, j = ij & 31;
        const float* pr = ps + r * NTRIL;
        int mn = i < j ? i : j, mx = i < j ? j : i;
        int bi = 32 + (i * (i - 1)) / 2, bj = 32 + (j * (j - 1)) / 2;
        float sum = 0.f;
        for (int k = 0; k < mn; k++)
            sum = fmaf(pr[bi + k], pr[bj + k], sum);
        if (i == j) {
            float d = pr[i] + BIAS_F;
            sum = fmaf(d, d, sum);
        } else {
            float lml = pr[32 + (mx * (mx - 1)) / 2 + mn];
            sum = fmaf(lml, pr[mn] + BIAS_F, sum);
        }
        out[(size_t)(row0 + r) * 1024 + ij] = sum;
    }
}

#define P_IN  32768
#define P_H1  294912
#define P_H2  557056
#define P_OU  819200
#define P_TOT 1089536

__global__ void prep_kernel(const float* __restrict__ Win, const float* __restrict__ Wh1,
                            const float* __restrict__ Wh2, const float* __restrict__ Wou,
                            const float* __restrict__ Wo)
{
    for (int e = blockIdx.x * blockDim.x + threadIdx.x; e < P_TOT;
         e += gridDim.x * blockDim.x) {
        float v; __nv_bfloat16 *ph, *pl; int o;
        if (e < P_IN) {
            int n = e >> 6, k = e & 63;
            v = (k < QDIM) ? __ldg(Win + k * HDIM + n) : 0.f;
            ph = g_Wi_h; pl = g_Wi_l; o = e;
        } else if (e < P_H1) {
            int t = e - P_IN, n = t >> 9, k = t & 511;
            v = __ldg(Wh1 + k * HDIM + n); ph = g_W1_h; pl = g_W1_l; o = t;
        } else if (e < P_H2) {
            int t = e - P_H1, n = t >> 9, k = t & 511;
            v = __ldg(Wh2 + k * HDIM + n); ph = g_W2_h; pl = g_W2_l; o = t;
        } else if (e < P_OU) {
            int t = e - P_H2, n = t >> 9, k = t & 511;
            v = __ldg(Wou + k * HDIM + n); ph = g_Wu_h; pl = g_Wu_l; o = t;
        } else {
            int t = e - P_OU, n = t >> 9, k = t & 511;
            v = __ldg(Wo + k * NTRIL + n); ph = g_Wo_h; pl = g_Wo_l; o = t;
        }
        __nv_bfloat16 h = __float2bfloat16(v);
        ph[o] = h;
        pl[o] = __float2bfloat16(v - __bfloat162float(h));
    }
}

extern "C" void kernel_launch(void* const* d_in, const int* in_sizes, int n_in,
                              void* d_out, int out_size)
{
    const float* q    = (const float*)d_in[0];
    const float* Win  = (const float*)d_in[1];
    const float* bin  = (const float*)d_in[2];
    const float* Wh1  = (const float*)d_in[3];
    const float* bh1  = (const float*)d_in[4];
    const float* Wh2  = (const float*)d_in[5];
    const float* bh2  = (const float*)d_in[6];
    const float* Wout = (const float*)d_in[7];
    const float* bout = (const float*)d_in[8];
    const float* Wo   = (const float*)d_in[9];
    const float* bo   = (const float*)d_in[10];
    float* out = (float*)d_out;

    const int B = in_sizes[0] / QDIM;   // 65536

    cudaFuncSetAttribute(main_kernel,
                         cudaFuncAttributeMaxDynamicSharedMemorySize, SMEM_BYTES);

    prep_kernel<<<148, 512>>>(Win, Wh1, Wh2, Wout, Wo);
    main_kernel<<<B / 64, 512, SMEM_BYTES>>>(q, bin, bh1, bh2, bout, bo, out);
}

// round 8
// speedup vs baseline: 1.6905x; 1.2751x over previous
#include <cuda_runtime.h>
#include <cuda_bf16.h>
#include <cstdint>

// CholeskyMMNet: mma.sync bf16 hi/lo split, B fragments pre-shuffled in gmem
// (direct LDG, no smem staging for weights). A (activations) smem-resident.
// prep: weights -> fragment layout; main: 5 GEMM layers; mm: M = L@L^T.

#define QDIM 32
#define HDIM 512
#define NTRIL 528
#define BIAS_F 2.0f

// fragment-layout weights: uint4 index ((S*16 + J)*4 + g)*32 + lane
//   g0 = hi, n8 blocks {0,1}; g1 = hi {2,3}; g2 = lo {0,1}; g3 = lo {2,3}
//   uint4 = { b(j,klo), b(j,khi), b(j+1,klo), b(j+1,khi) }
//   b(j,half)[lane] = pack2( W^T[n][k], W^T[n][k+1] ),
//   n = J*32 + j*8 + (lane>>2), k = S*16 + half*8 + 2*(lane&3)
__device__ uint4 g_Fi[2  * 16 * 4 * 32];   // layer0, K=32   (64KB)
__device__ uint4 g_F1[32 * 16 * 4 * 32];   // 1MB
__device__ uint4 g_F2[32 * 16 * 4 * 32];
__device__ uint4 g_Fu[32 * 16 * 4 * 32];
__device__ uint4 g_Fo[32 * 16 * 4 * 32];   // W_o cols 0..511
__device__ __nv_bfloat16 g_Wt_h[16 * 512], g_Wt_l[16 * 512];  // W_o cols 512..527 (transposed)
__device__ float g_Lp[65536ull * NTRIL];

// xs: [64 rows][2048B] = hi 1KB | lo 1KB per row, XOR-swizzled
#define XS(r,k,sel) ((r)*2048 + ((((sel)<<10) + ((k)<<1)) ^ (((r)&7)<<4)))
#define SMEM_BYTES 131072
#define MM_SMEM (64 * NTRIL * 4)

__device__ __forceinline__ uint32_t smem_u32(const void* p) {
    uint32_t a;
    asm("{ .reg .u64 t; cvta.to.shared.u64 t, %1; cvt.u32.u64 %0, t; }" : "=r"(a) : "l"(p));
    return a;
}

#define LDSM4(d0,d1,d2,d3, addr) \
    asm volatile("ldmatrix.sync.aligned.m8n8.x4.shared.b16 {%0,%1,%2,%3}, [%4];" \
        : "=r"(d0),"=r"(d1),"=r"(d2),"=r"(d3) : "r"(addr))

#define MMA16816(c, a0,a1,a2,a3, b0,b1) \
    asm volatile("mma.sync.aligned.m16n8k16.row.col.f32.bf16.bf16.f32 " \
        "{%0,%1,%2,%3}, {%4,%5,%6,%7}, {%8,%9}, {%0,%1,%2,%3};" \
        : "+f"((c)[0]),"+f"((c)[1]),"+f"((c)[2]),"+f"((c)[3]) \
        : "r"(a0),"r"(a1),"r"(a2),"r"(a3), "r"(b0),"r"(b1))

__device__ __forceinline__ void split2(float a, float b, uint32_t& h, uint32_t& l) {
    __nv_bfloat16 ha = __float2bfloat16(a), hb = __float2bfloat16(b);
    __nv_bfloat162 hp = __halves2bfloat162(ha, hb);
    __nv_bfloat162 lp = __halves2bfloat162(
        __float2bfloat16(a - __bfloat162float(ha)),
        __float2bfloat16(b - __bfloat162float(hb)));
    h = *(uint32_t*)&hp; l = *(uint32_t*)&lp;
}
__device__ __forceinline__ float rd2(const char* sm, int off0, int off1, int idx) {
    __nv_bfloat162 h = *(const __nv_bfloat162*)(sm + off0);
    __nv_bfloat162 l = *(const __nv_bfloat162*)(sm + off1);
    return idx ? (__bfloat162float(h.y) + __bfloat162float(l.y))
               : (__bfloat162float(h.x) + __bfloat162float(l.x));
}

__device__ __forceinline__ void ldB(uint4 b[4], const uint4* __restrict__ gF,
                                    int S, int warp, int lane) {
    const uint4* p = gF + ((size_t)(S * 16 + warp) * 4) * 32 + lane;
    b[0] = __ldg(p);       b[1] = __ldg(p + 32);
    b[2] = __ldg(p + 64);  b[3] = __ldg(p + 96);
}

// one k16 step: ldsm A (m64 hi/lo) + 48 MMA against B regs
__device__ __forceinline__ void do_step(uint32_t smb, int S, const uint4 bq[4],
                                        float* __restrict__ acc, int lane) {
    const int kk = S * 16 + ((lane >> 4) << 3);
    const int rb = lane & 15;
    #pragma unroll
    for (int mb = 0; mb < 4; mb++) {
        uint32_t ah0,ah1,ah2,ah3, al0,al1,al2,al3;
        const int r = mb * 16 + rb;
        LDSM4(ah0,ah1,ah2,ah3, smb + XS(r, kk, 0));
        LDSM4(al0,al1,al2,al3, smb + XS(r, kk, 1));
        float* A = acc + mb * 16;
        // j=0
        MMA16816(A+0,  ah0,ah1,ah2,ah3, bq[0].x, bq[0].y);
        MMA16816(A+0,  ah0,ah1,ah2,ah3, bq[2].x, bq[2].y);
        MMA16816(A+0,  al0,al1,al2,al3, bq[0].x, bq[0].y);
        // j=1
        MMA16816(A+4,  ah0,ah1,ah2,ah3, bq[0].z, bq[0].w);
        MMA16816(A+4,  ah0,ah1,ah2,ah3, bq[2].z, bq[2].w);
        MMA16816(A+4,  al0,al1,al2,al3, bq[0].z, bq[0].w);
        // j=2
        MMA16816(A+8,  ah0,ah1,ah2,ah3, bq[1].x, bq[1].y);
        MMA16816(A+8,  ah0,ah1,ah2,ah3, bq[3].x, bq[3].y);
        MMA16816(A+8,  al0,al1,al2,al3, bq[1].x, bq[1].y);
        // j=3
        MMA16816(A+12, ah0,ah1,ah2,ah3, bq[1].z, bq[1].w);
        MMA16816(A+12, ah0,ah1,ah2,ah3, bq[3].z, bq[3].w);
        MMA16816(A+12, al0,al1,al2,al3, bq[1].z, bq[1].w);
    }
}

// D[64][512] = X @ W^T; warp tile m64 x n32; epilogue to xs (or g_Lp when TO_LP)
template<int NS, bool RELU, bool RES, bool TO_LP>
__device__ void tc_layer(char* __restrict__ sm, uint32_t smb,
                         const uint4* __restrict__ gF,
                         const float* __restrict__ bias, int row0)
{
    const int tid = threadIdx.x, warp = tid >> 5, lane = tid & 31;
    float acc[64];
    #pragma unroll
    for (int i = 0; i < 64; i++) acc[i] = 0.f;

    uint4 b0[4], b1[4];
    ldB(b0, gF, 0, warp, lane);
    #pragma unroll 1
    for (int S = 0; S < NS; S += 2) {
        if (S + 1 < NS) ldB(b1, gF, S + 1, warp, lane);
        do_step(smb, S, b0, acc, lane);
        if (S + 1 < NS) {
            if (S + 2 < NS) ldB(b0, gF, S + 2, warp, lane);
            do_step(smb, S + 1, b1, acc, lane);
        }
    }
    __syncthreads();   // all ldsm reads of xs complete before epilogue writes

    // epilogue (for TO_LP: writes g_Lp, xs untouched)
    #pragma unroll
    for (int mb = 0; mb < 4; mb++)
        #pragma unroll
        for (int j = 0; j < 4; j++) {
            const int c  = warp * 32 + j * 8 + 2 * (lane & 3);
            const int r0 = mb * 16 + (lane >> 2), r1 = r0 + 8;
            const float* a = acc + (mb * 4 + j) * 4;
            float b0v = __ldg(bias + c), b1v = __ldg(bias + c + 1);
            float y00 = a[0] + b0v, y01 = a[1] + b1v;
            float y10 = a[2] + b0v, y11 = a[3] + b1v;
            if (RELU) {
                y00 = fmaxf(y00, 0.f); y01 = fmaxf(y01, 0.f);
                y10 = fmaxf(y10, 0.f); y11 = fmaxf(y11, 0.f);
            }
            if (RES) {
                y00 += rd2(sm, XS(r0, c, 0), XS(r0, c, 1), 0);
                y01 += rd2(sm, XS(r0, c, 0), XS(r0, c, 1), 1);
                y10 += rd2(sm, XS(r1, c, 0), XS(r1, c, 1), 0);
                y11 += rd2(sm, XS(r1, c, 0), XS(r1, c, 1), 1);
            }
            if (TO_LP) {
                float* lp0 = g_Lp + (size_t)(row0 + r0) * NTRIL + c;
                float* lp1 = g_Lp + (size_t)(row0 + r1) * NTRIL + c;
                lp0[0] = y00; lp0[1] = y01;
                lp1[0] = y10; lp1[1] = y11;
            } else {
                uint32_t h, l;
                split2(y00, y01, h, l);
                *(uint32_t*)(sm + XS(r0, c, 0)) = h;
                *(uint32_t*)(sm + XS(r0, c, 1)) = l;
                split2(y10, y11, h, l);
                *(uint32_t*)(sm + XS(r1, c, 0)) = h;
                *(uint32_t*)(sm + XS(r1, c, 1)) = l;
            }
        }

    if (TO_LP) {
        // W_o cols 512..527: scalar tail (xs is still intact)
        const int tr = tid >> 3, tcc = (tid & 7) * 2;
        const __nv_bfloat16* w0h = g_Wt_h + tcc * 512;
        const __nv_bfloat16* w0l = g_Wt_l + tcc * 512;
        const __nv_bfloat16* w1h = w0h + 512;
        const __nv_bfloat16* w1l = w0l + 512;
        float t0 = 0.f, t1 = 0.f;
        for (int k = 0; k < 512; k += 2) {
            float x0 = rd2(sm, XS(tr, k, 0), XS(tr, k, 1), 0);
            float x1 = rd2(sm, XS(tr, k, 0), XS(tr, k, 1), 1);
            float a0 = __bfloat162float(w0h[k])   + __bfloat162float(w0l[k]);
            float a1 = __bfloat162float(w0h[k+1]) + __bfloat162float(w0l[k+1]);
            float c0 = __bfloat162float(w1h[k])   + __bfloat162float(w1l[k]);
            float c1 = __bfloat162float(w1h[k+1]) + __bfloat162float(w1l[k+1]);
            t0 = fmaf(x0, a0, fmaf(x1, a1, t0));
            t1 = fmaf(x0, c0, fmaf(x1, c1, t1));
        }
        g_Lp[(size_t)(row0 + tr) * NTRIL + 512 + tcc]     = t0 + __ldg(bias + 512 + tcc);
        g_Lp[(size_t)(row0 + tr) * NTRIL + 512 + tcc + 1] = t1 + __ldg(bias + 513 + tcc);
    }
    __syncthreads();
}

__global__ void __launch_bounds__(512, 1)
main_kernel(const float* __restrict__ q,
            const float* __restrict__ bin, const float* __restrict__ bh1,
            const float* __restrict__ bh2, const float* __restrict__ bout,
            const float* __restrict__ bo)
{
    extern __shared__ char sm[];
    const uint32_t smb = smem_u32(sm);
    const int tid = threadIdx.x;
    const int row0 = blockIdx.x * 64;

    {   // stage q (64x32 fp32) into xs hi/lo
        int r = tid >> 3, kq = (tid & 7) * 4;
        float4 v = *(const float4*)(q + (size_t)(row0 + r) * QDIM + kq);
        uint32_t h, l;
        split2(v.x, v.y, h, l);
        *(uint32_t*)(sm + XS(r, kq, 0)) = h;
        *(uint32_t*)(sm + XS(r, kq, 1)) = l;
        split2(v.z, v.w, h, l);
        *(uint32_t*)(sm + XS(r, kq + 2, 0)) = h;
        *(uint32_t*)(sm + XS(r, kq + 2, 1)) = l;
    }
    __syncthreads();

    tc_layer<2,  true,  false, false>(sm, smb, g_Fi, bin,  row0);
    tc_layer<32, true,  true,  false>(sm, smb, g_F1, bh1,  row0);
    tc_layer<32, true,  true,  false>(sm, smb, g_F2, bh2,  row0);
    tc_layer<32, false, false, false>(sm, smb, g_Fu, bout, row0);
    tc_layer<32, false, false, true >(sm, smb, g_Fo, bo,   row0);
}

// ---------------- prep: weights -> fragment layout ----------------
#define FI_U32   (2 * 16 * 4 * 32 * 4)        // 16384
#define FL_U32   (32 * 16 * 4 * 32 * 4)       // 262144
#define MAIN_U32 (FI_U32 + 4 * FL_U32)        // 1064960
#define TAIL_E   (16 * 512)

__global__ void prep_kernel(const float* __restrict__ Win, const float* __restrict__ Wh1,
                            const float* __restrict__ Wh2, const float* __restrict__ Wou,
                            const float* __restrict__ Wo)
{
    const int total = MAIN_U32 + TAIL_E;
    for (int e = blockIdx.x * blockDim.x + threadIdx.x; e < total;
         e += gridDim.x * blockDim.x) {
        if (e < MAIN_U32) {
            const float* W; uint32_t* dst; int t, ncols;
            if (e < FI_U32) { W = Win; dst = (uint32_t*)g_Fi; t = e; ncols = 512; }
            else {
                int le = e - FI_U32, ly = le / FL_U32;
                t = le - ly * FL_U32;
                ncols = (ly == 3) ? 528 : 512;
                W   = (ly == 0) ? Wh1 : (ly == 1) ? Wh2 : (ly == 2) ? Wou : Wo;
                dst = (uint32_t*)((ly == 0) ? g_F1 : (ly == 1) ? g_F2 :
                                  (ly == 2) ? g_Fu : g_Fo);
            }
            // t = S*8192 + J*512 + g*128 + l*4 + c
            int c = t & 3, l = (t >> 2) & 31, g = (t >> 7) & 3;
            int J = (t >> 9) & 15, S = t >> 13;
            int jl  = (g & 1) * 2 + (c >> 1);
            int sel = g >> 1;
            int n   = J * 32 + jl * 8 + (l >> 2);
            int k0  = S * 16 + (c & 1) * 8 + 2 * (l & 3);
            float v0 = __ldg(W + (size_t)k0 * ncols + n);
            float v1 = __ldg(W + (size_t)(k0 + 1) * ncols + n);
            __nv_bfloat16 h0 = __float2bfloat16(v0), h1 = __float2bfloat16(v1);
            __nv_bfloat16 o0, o1;
            if (sel == 0) { o0 = h0; o1 = h1; }
            else {
                o0 = __float2bfloat16(v0 - __bfloat162float(h0));
                o1 = __float2bfloat16(v1 - __bfloat162float(h1));
            }
            __nv_bfloat162 p = __halves2bfloat162(o0, o1);
            dst[t] = *(uint32_t*)&p;
        } else {
            int t = e - MAIN_U32;
            int nt = t >> 9, k = t & 511;
            float v = __ldg(Wo + (size_t)k * 528 + 512 + nt);
            __nv_bfloat16 h = __float2bfloat16(v);
            g_Wt_h[nt * 512 + k] = h;
            g_Wt_l[nt * 512 + k] = __float2bfloat16(v - __bfloat162float(h));
        }
    }
}

// ---------------- mm: M = L @ L^T (verified fp32 path) ----------------
__global__ void __launch_bounds__(512) mm_kernel(float* __restrict__ out)
{
    extern __shared__ float ps[];
    const int tid = threadIdx.x;
    const int row0 = blockIdx.x * 64;

    const float4* lp4 = (const float4*)(g_Lp + (size_t)row0 * NTRIL);
    for (int i = tid; i < (64 * NTRIL) / 4; i += 512)
        ((float4*)ps)[i] = __ldg(lp4 + i);
    __syncthreads();

    for (int idx = tid; idx < 64 * QDIM * QDIM; idx += 512) {
        int r = idx >> 10, ij = idx & 1023, i = ij >> 5, j = ij & 31;
        const float* pr = ps + r * NTRIL;
        int mn = i < j ? i : j, mx = i < j ? j : i;
        int bi = 32 + (i * (i - 1)) / 2, bj = 32 + (j * (j - 1)) / 2;
        float sum = 0.f;
        for (int k = 0; k < mn; k++)
            sum = fmaf(pr[bi + k], pr[bj + k], sum);
        if (i == j) {
            float d = pr[i] + BIAS_F;
            sum = fmaf(d, d, sum);
        } else {
            float lml = pr[32 + (mx * (mx - 1)) / 2 + mn];
            sum = fmaf(lml, pr[mn] + BIAS_F, sum);
        }
        out[(size_t)(row0 + r) * 1024 + ij] = sum;
    }
}

extern "C" void kernel_launch(void* const* d_in, const int* in_sizes, int n_in,
                              void* d_out, int out_size)
{
    const float* q    = (const float*)d_in[0];
    const float* Win  = (const float*)d_in[1];
    const float* bin  = (const float*)d_in[2];
    const float* Wh1  = (const float*)d_in[3];
    const float* bh1  = (const float*)d_in[4];
    const float* Wh2  = (const float*)d_in[5];
    const float* bh2  = (const float*)d_in[6];
    const float* Wout = (const float*)d_in[7];
    const float* bout = (const float*)d_in[8];
    const float* Wo   = (const float*)d_in[9];
    const float* bo   = (const float*)d_in[10];
    float* out = (float*)d_out;

    const int B = in_sizes[0] / QDIM;   // 65536

    cudaFuncSetAttribute(main_kernel,
                         cudaFuncAttributeMaxDynamicSharedMemorySize, SMEM_BYTES);
    cudaFuncSetAttribute(mm_kernel,
                         cudaFuncAttributeMaxDynamicSharedMemorySize, MM_SMEM);

    prep_kernel<<<148, 512>>>(Win, Wh1, Wh2, Wout, Wo);
    main_kernel<<<B / 64, 512, SMEM_BYTES>>>(q, bin, bh1, bh2, bout, bo);
    mm_kernel<<<B / 64, 512, MM_SMEM>>>(out);
}

// round 9
// speedup vs baseline: 1.8035x; 1.0668x over previous
#include <cuda_runtime.h>
#include <cuda_bf16.h>
#include <cstdint>

// CholeskyMMNet: mma.sync bf16 hi/lo split; B fragments pre-shuffled in gmem
// (direct LDG, no smem staging); A smem-resident; L_params + L@L^T fused
// in-kernel via smem overlay (no gmem scratch round-trip).

#define QDIM 32
#define HDIM 512
#define NTRIL 528
#define BIAS_F 2.0f

// fragment-layout weights: uint4 index ((S*16 + J)*4 + g)*32 + lane
//   g0 = hi, n8 blocks {0,1}; g1 = hi {2,3}; g2 = lo {0,1}; g3 = lo {2,3}
__device__ uint4 g_Fi[2  * 16 * 4 * 32];
__device__ uint4 g_F1[32 * 16 * 4 * 32];
__device__ uint4 g_F2[32 * 16 * 4 * 32];
__device__ uint4 g_Fu[32 * 16 * 4 * 32];
__device__ uint4 g_Fo[32 * 16 * 4 * 32];   // W_o cols 0..511
__device__ __nv_bfloat16 g_Wt_h[16 * 512], g_Wt_l[16 * 512];  // W_o cols 512..527 (transposed)

// xs: [64 rows][2048B] = hi 1KB | lo 1KB per row, XOR-swizzled (bytes 0..128K)
// Lp overlay: [64][528] fp32 at byte 0 (valid only after final epilogue)
#define XS(r,k,sel) ((r)*2048 + ((((sel)<<10) + ((k)<<1)) ^ (((r)&7)<<4)))
#define SMEM_BYTES 135168

__device__ __forceinline__ uint32_t smem_u32(const void* p) {
    uint32_t a;
    asm("{ .reg .u64 t; cvta.to.shared.u64 t, %1; cvt.u32.u64 %0, t; }" : "=r"(a) : "l"(p));
    return a;
}

#define LDSM4(d0,d1,d2,d3, addr) \
    asm volatile("ldmatrix.sync.aligned.m8n8.x4.shared.b16 {%0,%1,%2,%3}, [%4];" \
        : "=r"(d0),"=r"(d1),"=r"(d2),"=r"(d3) : "r"(addr))

#define MMA16816(c, a0,a1,a2,a3, b0,b1) \
    asm volatile("mma.sync.aligned.m16n8k16.row.col.f32.bf16.bf16.f32 " \
        "{%0,%1,%2,%3}, {%4,%5,%6,%7}, {%8,%9}, {%0,%1,%2,%3};" \
        : "+f"((c)[0]),"+f"((c)[1]),"+f"((c)[2]),"+f"((c)[3]) \
        : "r"(a0),"r"(a1),"r"(a2),"r"(a3), "r"(b0),"r"(b1))

__device__ __forceinline__ void split2(float a, float b, uint32_t& h, uint32_t& l) {
    __nv_bfloat16 ha = __float2bfloat16(a), hb = __float2bfloat16(b);
    __nv_bfloat162 hp = __halves2bfloat162(ha, hb);
    __nv_bfloat162 lp = __halves2bfloat162(
        __float2bfloat16(a - __bfloat162float(ha)),
        __float2bfloat16(b - __bfloat162float(hb)));
    h = *(uint32_t*)&hp; l = *(uint32_t*)&lp;
}
__device__ __forceinline__ float rd2(const char* sm, int off0, int off1, int idx) {
    __nv_bfloat162 h = *(const __nv_bfloat162*)(sm + off0);
    __nv_bfloat162 l = *(const __nv_bfloat162*)(sm + off1);
    return idx ? (__bfloat162float(h.y) + __bfloat162float(l.y))
               : (__bfloat162float(h.x) + __bfloat162float(l.x));
}

__device__ __forceinline__ void ldB(uint4 b[4], const uint4* __restrict__ gF,
                                    int S, int warp, int lane) {
    const uint4* p = gF + ((size_t)(S * 16 + warp) * 4) * 32 + lane;
    b[0] = __ldg(p);       b[1] = __ldg(p + 32);
    b[2] = __ldg(p + 64);  b[3] = __ldg(p + 96);
}

// one k16 step: per mb, LDSM ah+al then hh, hl, lh (A frags die early)
__device__ __forceinline__ void do_step(uint32_t smb, int S, const uint4 bq[4],
                                        float* __restrict__ acc, int lane) {
    const int kk = S * 16 + ((lane >> 4) << 3);
    const int rb = lane & 15;
    #pragma unroll
    for (int mb = 0; mb < 4; mb++) {
        uint32_t ah0,ah1,ah2,ah3, al0,al1,al2,al3;
        const int r = mb * 16 + rb;
        LDSM4(ah0,ah1,ah2,ah3, smb + XS(r, kk, 0));
        LDSM4(al0,al1,al2,al3, smb + XS(r, kk, 1));
        float* A = acc + mb * 16;
        // hh
        MMA16816(A+0,  ah0,ah1,ah2,ah3, bq[0].x, bq[0].y);
        MMA16816(A+4,  ah0,ah1,ah2,ah3, bq[0].z, bq[0].w);
        MMA16816(A+8,  ah0,ah1,ah2,ah3, bq[1].x, bq[1].y);
        MMA16816(A+12, ah0,ah1,ah2,ah3, bq[1].z, bq[1].w);
        // hl (ah * b_lo)
        MMA16816(A+0,  ah0,ah1,ah2,ah3, bq[2].x, bq[2].y);
        MMA16816(A+4,  ah0,ah1,ah2,ah3, bq[2].z, bq[2].w);
        MMA16816(A+8,  ah0,ah1,ah2,ah3, bq[3].x, bq[3].y);
        MMA16816(A+12, ah0,ah1,ah2,ah3, bq[3].z, bq[3].w);
        // lh (al * b_hi)
        MMA16816(A+0,  al0,al1,al2,al3, bq[0].x, bq[0].y);
        MMA16816(A+4,  al0,al1,al2,al3, bq[0].z, bq[0].w);
        MMA16816(A+8,  al0,al1,al2,al3, bq[1].x, bq[1].y);
        MMA16816(A+12, al0,al1,al2,al3, bq[1].z, bq[1].w);
    }
}

// D[64][512] = X @ W^T; warp tile m64 x n32
// TO_LP: write fp32 L_params overlay into smem (+ scalar tail cols 512..527)
template<int NS, bool RELU, bool RES, bool TO_LP>
__device__ void tc_layer(char* __restrict__ sm, uint32_t smb,
                         const uint4* __restrict__ gF,
                         const float* __restrict__ bias)
{
    const int tid = threadIdx.x, warp = tid >> 5, lane = tid & 31;
    float acc[64];
    #pragma unroll
    for (int i = 0; i < 64; i++) acc[i] = 0.f;

    uint4 b0[4], b1[4];
    ldB(b0, gF, 0, warp, lane);
    #pragma unroll 1
    for (int S = 0; S < NS; S += 2) {
        if (S + 1 < NS) ldB(b1, gF, S + 1, warp, lane);
        do_step(smb, S, b0, acc, lane);
        if (S + 1 < NS) {
            if (S + 2 < NS) ldB(b0, gF, S + 2, warp, lane);
            do_step(smb, S + 1, b1, acc, lane);
        }
    }
    __syncthreads();   // all ldsm reads of xs complete

    float t0 = 0.f, t1 = 0.f;
    int tr = 0, tcc = 0;
    if (TO_LP) {
        // scalar tail (cols 512..527) reads xs BEFORE overlay writes
        tr = tid >> 3; tcc = (tid & 7) * 2;
        const __nv_bfloat16* w0h = g_Wt_h + tcc * 512;
        const __nv_bfloat16* w0l = g_Wt_l + tcc * 512;
        const __nv_bfloat16* w1h = w0h + 512;
        const __nv_bfloat16* w1l = w0l + 512;
        for (int k = 0; k < 512; k += 2) {
            float x0 = rd2(sm, XS(tr, k, 0), XS(tr, k, 1), 0);
            float x1 = rd2(sm, XS(tr, k, 0), XS(tr, k, 1), 1);
            float a0 = __bfloat162float(w0h[k])   + __bfloat162float(w0l[k]);
            float a1 = __bfloat162float(w0h[k+1]) + __bfloat162float(w0l[k+1]);
            float c0 = __bfloat162float(w1h[k])   + __bfloat162float(w1l[k]);
            float c1 = __bfloat162float(w1h[k+1]) + __bfloat162float(w1l[k+1]);
            t0 = fmaf(x0, a0, fmaf(x1, a1, t0));
            t1 = fmaf(x0, c0, fmaf(x1, c1, t1));
        }
        __syncthreads();   // tail reads done before overlay overwrites xs
    }

    #pragma unroll
    for (int mb = 0; mb < 4; mb++)
        #pragma unroll
        for (int j = 0; j < 4; j++) {
            const int c  = warp * 32 + j * 8 + 2 * (lane & 3);
            const int r0 = mb * 16 + (lane >> 2), r1 = r0 + 8;
            const float* a = acc + (mb * 4 + j) * 4;
            float b0v = __ldg(bias + c), b1v = __ldg(bias + c + 1);
            float y00 = a[0] + b0v, y01 = a[1] + b1v;
            float y10 = a[2] + b0v, y11 = a[3] + b1v;
            if (RELU) {
                y00 = fmaxf(y00, 0.f); y01 = fmaxf(y01, 0.f);
                y10 = fmaxf(y10, 0.f); y11 = fmaxf(y11, 0.f);
            }
            if (RES) {
                y00 += rd2(sm, XS(r0, c, 0), XS(r0, c, 1), 0);
                y01 += rd2(sm, XS(r0, c, 0), XS(r0, c, 1), 1);
                y10 += rd2(sm, XS(r1, c, 0), XS(r1, c, 1), 0);
                y11 += rd2(sm, XS(r1, c, 0), XS(r1, c, 1), 1);
            }
            if (TO_LP) {
                float* lp = (float*)sm;
                lp[r0 * NTRIL + c] = y00; lp[r0 * NTRIL + c + 1] = y01;
                lp[r1 * NTRIL + c] = y10; lp[r1 * NTRIL + c + 1] = y11;
            } else {
                uint32_t h, l;
                split2(y00, y01, h, l);
                *(uint32_t*)(sm + XS(r0, c, 0)) = h;
                *(uint32_t*)(sm + XS(r0, c, 1)) = l;
                split2(y10, y11, h, l);
                *(uint32_t*)(sm + XS(r1, c, 0)) = h;
                *(uint32_t*)(sm + XS(r1, c, 1)) = l;
            }
        }
    if (TO_LP) {
        float* lp = (float*)sm;
        lp[tr * NTRIL + 512 + tcc]     = t0 + __ldg(bias + 512 + tcc);
        lp[tr * NTRIL + 512 + tcc + 1] = t1 + __ldg(bias + 513 + tcc);
    }
    __syncthreads();
}

__global__ void __launch_bounds__(512, 1)
main_kernel(const float* __restrict__ q,
            const float* __restrict__ bin, const float* __restrict__ bh1,
            const float* __restrict__ bh2, const float* __restrict__ bout,
            const float* __restrict__ bo,  float* __restrict__ out)
{
    extern __shared__ char sm[];
    const uint32_t smb = smem_u32(sm);
    const int tid = threadIdx.x;
    const int row0 = blockIdx.x * 64;

    {   // stage q (64x32 fp32) into xs hi/lo
        int r = tid >> 3, kq = (tid & 7) * 4;
        float4 v = *(const float4*)(q + (size_t)(row0 + r) * QDIM + kq);
        uint32_t h, l;
        split2(v.x, v.y, h, l);
        *(uint32_t*)(sm + XS(r, kq, 0)) = h;
        *(uint32_t*)(sm + XS(r, kq, 1)) = l;
        split2(v.z, v.w, h, l);
        *(uint32_t*)(sm + XS(r, kq + 2, 0)) = h;
        *(uint32_t*)(sm + XS(r, kq + 2, 1)) = l;
    }
    __syncthreads();

    tc_layer<2,  true,  false, false>(sm, smb, g_Fi, bin);
    tc_layer<32, true,  true,  false>(sm, smb, g_F1, bh1);
    tc_layer<32, true,  true,  false>(sm, smb, g_F2, bh2);
    tc_layer<32, false, false, false>(sm, smb, g_Fu, bout);
    tc_layer<32, false, false, true >(sm, smb, g_Fo, bo);

    // M = L @ L^T from Lp smem overlay (verified fp32 path)
    const float* ps = (const float*)sm;
    for (int idx = tid; idx < 64 * QDIM * QDIM; idx += 512) {
        int r = idx >> 10, ij = idx & 1023, i = ij >> 5, j = ij & 31;
        const float* pr = ps + r * NTRIL;
        int mn = i < j ? i : j, mx = i < j ? j : i;
        int bi = 32 + (i * (i - 1)) / 2, bj = 32 + (j * (j - 1)) / 2;
        float sum = 0.f;
        for (int k = 0; k < mn; k++)
            sum = fmaf(pr[bi + k], pr[bj + k], sum);
        if (i == j) {
            float d = pr[i] + BIAS_F;
            sum = fmaf(d, d, sum);
        } else {
            float lml = pr[32 + (mx * (mx - 1)) / 2 + mn];
            sum = fmaf(lml, pr[mn] + BIAS_F, sum);
        }
        out[(size_t)(row0 + r) * 1024 + ij] = sum;
    }
}

// ---------------- prep: weights -> fragment layout ----------------
#define FI_U32   (2 * 16 * 4 * 32 * 4)
#define FL_U32   (32 * 16 * 4 * 32 * 4)
#define MAIN_U32 (FI_U32 + 4 * FL_U32)
#define TAIL_E   (16 * 512)

__global__ void prep_kernel(const float* __restrict__ Win, const float* __restrict__ Wh1,
                            const float* __restrict__ Wh2, const float* __restrict__ Wou,
                            const float* __restrict__ Wo)
{
    const int total = MAIN_U32 + TAIL_E;
    for (int e = blockIdx.x * blockDim.x + threadIdx.x; e < total;
         e += gridDim.x * blockDim.x) {
        if (e < MAIN_U32) {
            const float* W; uint32_t* dst; int t, ncols;
            if (e < FI_U32) { W = Win; dst = (uint32_t*)g_Fi; t = e; ncols = 512; }
            else {
                int le = e - FI_U32, ly = le / FL_U32;
                t = le - ly * FL_U32;
                ncols = (ly == 3) ? 528 : 512;
                W   = (ly == 0) ? Wh1 : (ly == 1) ? Wh2 : (ly == 2) ? Wou : Wo;
                dst = (uint32_t*)((ly == 0) ? g_F1 : (ly == 1) ? g_F2 :
                                  (ly == 2) ? g_Fu : g_Fo);
            }
            int c = t & 3, l = (t >> 2) & 31, g = (t >> 7) & 3;
            int J = (t >> 9) & 15, S = t >> 13;
            int jl  = (g & 1) * 2 + (c >> 1);
            int sel = g >> 1;
            int n   = J * 32 + jl * 8 + (l >> 2);
            int k0  = S * 16 + (c & 1) * 8 + 2 * (l & 3);
            float v0 = __ldg(W + (size_t)k0 * ncols + n);
            float v1 = __ldg(W + (size_t)(k0 + 1) * ncols + n);
            __nv_bfloat16 h0 = __float2bfloat16(v0), h1 = __float2bfloat16(v1);
            __nv_bfloat16 o0, o1;
            if (sel == 0) { o0 = h0; o1 = h1; }
            else {
                o0 = __float2bfloat16(v0 - __bfloat162float(h0));
                o1 = __float2bfloat16(v1 - __bfloat162float(h1));
            }
            __nv_bfloat162 p = __halves2bfloat162(o0, o1);
            dst[t] = *(uint32_t*)&p;
        } else {
            int t = e - MAIN_U32;
            int nt = t >> 9, k = t & 511;
            float v = __ldg(Wo + (size_t)k * 528 + 512 + nt);
            __nv_bfloat16 h = __float2bfloat16(v);
            g_Wt_h[nt * 512 + k] = h;
            g_Wt_l[nt * 512 + k] = __float2bfloat16(v - __bfloat162float(h));
        }
    }
}

extern "C" void kernel_launch(void* const* d_in, const int* in_sizes, int n_in,
                              void* d_out, int out_size)
{
    const float* q    = (const float*)d_in[0];
    const float* Win  = (const float*)d_in[1];
    const float* bin  = (const float*)d_in[2];
    const float* Wh1  = (const float*)d_in[3];
    const float* bh1  = (const float*)d_in[4];
    const float* Wh2  = (const float*)d_in[5];
    const float* bh2  = (const float*)d_in[6];
    const float* Wout = (const float*)d_in[7];
    const float* bout = (const float*)d_in[8];
    const float* Wo   = (const float*)d_in[9];
    const float* bo   = (const float*)d_in[10];
    float* out = (float*)d_out;

    const int B = in_sizes[0] / QDIM;   // 65536

    cudaFuncSetAttribute(main_kernel,
                         cudaFuncAttributeMaxDynamicSharedMemorySize, SMEM_BYTES);

    prep_kernel<<<148, 512>>>(Win, Wh1, Wh2, Wout, Wo);
    main_kernel<<<B / 64, 512, SMEM_BYTES>>>(q, bin, bh1, bh2, bout, bo, out);
}

// round 10
// speedup vs baseline: 1.8714x; 1.0376x over previous
#include <cuda_runtime.h>
#include <cuda_bf16.h>
#include <cstdint>

// CholeskyMMNet: mma.sync bf16 hi/lo split; B fragments pre-shuffled in gmem
// (direct LDG); A smem-resident; 32 rows/CTA, 256 thr, 2 CTAs/SM for overlap.

#define QDIM 32
#define HDIM 512
#define NTRIL 528
#define BIAS_F 2.0f

// fragment-layout weights: uint4 index ((S*16 + J)*4 + g)*32 + lane
//   g0 = hi, n8 blocks {0,1}; g1 = hi {2,3}; g2 = lo {0,1}; g3 = lo {2,3}
__device__ uint4 g_Fi[2  * 16 * 4 * 32];
__device__ uint4 g_F1[32 * 16 * 4 * 32];
__device__ uint4 g_F2[32 * 16 * 4 * 32];
__device__ uint4 g_Fu[32 * 16 * 4 * 32];
__device__ uint4 g_Fo[32 * 16 * 4 * 32];   // W_o cols 0..511
__device__ __nv_bfloat16 g_Wt_h[16 * 512], g_Wt_l[16 * 512];  // W_o cols 512..527

// xs: [32 rows][2048B] = hi 1KB | lo 1KB per row, XOR-swizzled (0..64K)
// Lp overlay: [32][528] fp32 at byte 0 (valid only after final epilogue)
#define XS(r,k,sel) ((r)*2048 + ((((sel)<<10) + ((k)<<1)) ^ (((r)&7)<<4)))
#define SMEM_BYTES 67840

__device__ __forceinline__ uint32_t smem_u32(const void* p) {
    uint32_t a;
    asm("{ .reg .u64 t; cvta.to.shared.u64 t, %1; cvt.u32.u64 %0, t; }" : "=r"(a) : "l"(p));
    return a;
}

#define LDSM4(d, addr) \
    asm volatile("ldmatrix.sync.aligned.m8n8.x4.shared.b16 {%0,%1,%2,%3}, [%4];" \
        : "=r"((d)[0]),"=r"((d)[1]),"=r"((d)[2]),"=r"((d)[3]) : "r"(addr))

#define MMA16816(c, a, b0, b1) \
    asm volatile("mma.sync.aligned.m16n8k16.row.col.f32.bf16.bf16.f32 " \
        "{%0,%1,%2,%3}, {%4,%5,%6,%7}, {%8,%9}, {%0,%1,%2,%3};" \
        : "+f"((c)[0]),"+f"((c)[1]),"+f"((c)[2]),"+f"((c)[3]) \
        : "r"((a)[0]),"r"((a)[1]),"r"((a)[2]),"r"((a)[3]), "r"(b0),"r"(b1))

__device__ __forceinline__ void split2(float a, float b, uint32_t& h, uint32_t& l) {
    __nv_bfloat16 ha = __float2bfloat16(a), hb = __float2bfloat16(b);
    __nv_bfloat162 hp = __halves2bfloat162(ha, hb);
    __nv_bfloat162 lp = __halves2bfloat162(
        __float2bfloat16(a - __bfloat162float(ha)),
        __float2bfloat16(b - __bfloat162float(hb)));
    h = *(uint32_t*)&hp; l = *(uint32_t*)&lp;
}
__device__ __forceinline__ float rd2(const char* sm, int off0, int off1, int idx) {
    __nv_bfloat162 h = *(const __nv_bfloat162*)(sm + off0);
    __nv_bfloat162 l = *(const __nv_bfloat162*)(sm + off1);
    return idx ? (__bfloat162float(h.y) + __bfloat162float(l.y))
               : (__bfloat162float(h.x) + __bfloat162float(l.x));
}

__device__ __forceinline__ void ldB4(uint4* b, const uint4* __restrict__ gF,
                                     int S, int J, int lane) {
    const uint4* p = gF + ((size_t)(S * 16 + J) * 4) * 32 + lane;
    b[0] = __ldg(p);       b[1] = __ldg(p + 32);
    b[2] = __ldg(p + 64);  b[3] = __ldg(p + 96);
}

// 12 MMAs: hh (q0,q1), hl (q2,q3), lh (q0,q1) into acc block A[0..15]
__device__ __forceinline__ void mma12(float* A, const uint32_t ah[4], const uint32_t al[4],
                                      const uint4& q0, const uint4& q1,
                                      const uint4& q2, const uint4& q3) {
    MMA16816(A+0,  ah, q0.x, q0.y); MMA16816(A+4,  ah, q0.z, q0.w);
    MMA16816(A+8,  ah, q1.x, q1.y); MMA16816(A+12, ah, q1.z, q1.w);
    MMA16816(A+0,  ah, q2.x, q2.y); MMA16816(A+4,  ah, q2.z, q2.w);
    MMA16816(A+8,  ah, q3.x, q3.y); MMA16816(A+12, ah, q3.z, q3.w);
    MMA16816(A+0,  al, q0.x, q0.y); MMA16816(A+4,  al, q0.z, q0.w);
    MMA16816(A+8,  al, q1.x, q1.y); MMA16816(A+12, al, q1.z, q1.w);
}

// D[32][512] = X @ W^T; warp tile m32 x n64 (J blocks 2w, 2w+1)
// acc layout: [mb(2)][Jl(2)][j(4)][4] -> acc[mb*32 + Jl*16 + j*4]
template<int NS, bool RELU, bool RES, bool TO_LP>
__device__ void tc_layer(char* __restrict__ sm, uint32_t smb,
                         const uint4* __restrict__ gF,
                         const float* __restrict__ bias)
{
    const int tid = threadIdx.x, warp = tid >> 5, lane = tid & 31;
    float acc[64];
    #pragma unroll
    for (int i = 0; i < 64; i++) acc[i] = 0.f;

    uint4 bq[8];
    ldB4(bq,     gF, 0, 2 * warp,     lane);
    ldB4(bq + 4, gF, 0, 2 * warp + 1, lane);

    #pragma unroll 1
    for (int S = 0; S < NS; S++) {
        const int kk = S * 16 + ((lane >> 4) << 3);
        const int rb = lane & 15;
        uint32_t ah0[4], al0[4], ah1[4], al1[4];
        LDSM4(ah0, smb + XS(rb, kk, 0));
        LDSM4(al0, smb + XS(rb, kk, 1));
        mma12(acc +  0, ah0, al0, bq[0], bq[1], bq[2], bq[3]);
        LDSM4(ah1, smb + XS(16 + rb, kk, 0));
        LDSM4(al1, smb + XS(16 + rb, kk, 1));
        mma12(acc + 32, ah1, al1, bq[0], bq[1], bq[2], bq[3]);
        if (S + 1 < NS) ldB4(bq, gF, S + 1, 2 * warp, lane);   // overlap J1 MMAs
        mma12(acc + 16, ah0, al0, bq[4], bq[5], bq[6], bq[7]);
        mma12(acc + 48, ah1, al1, bq[4], bq[5], bq[6], bq[7]);
        if (S + 1 < NS) ldB4(bq + 4, gF, S + 1, 2 * warp + 1, lane);
    }
    __syncthreads();   // all ldsm reads of xs complete

    float t0 = 0.f, t1 = 0.f;
    int tr = 0, tcc = 0;
    if (TO_LP) {
        // scalar tail (cols 512..527) reads xs BEFORE overlay writes
        tr = tid >> 3; tcc = (tid & 7) * 2;
        const __nv_bfloat16* w0h = g_Wt_h + tcc * 512;
        const __nv_bfloat16* w0l = g_Wt_l + tcc * 512;
        const __nv_bfloat16* w1h = w0h + 512;
        const __nv_bfloat16* w1l = w0l + 512;
        for (int k = 0; k < 512; k += 2) {
            float x0 = rd2(sm, XS(tr, k, 0), XS(tr, k, 1), 0);
            float x1 = rd2(sm, XS(tr, k, 0), XS(tr, k, 1), 1);
            float a0 = __bfloat162float(w0h[k])   + __bfloat162float(w0l[k]);
            float a1 = __bfloat162float(w0h[k+1]) + __bfloat162float(w0l[k+1]);
            float c0 = __bfloat162float(w1h[k])   + __bfloat162float(w1l[k]);
            float c1 = __bfloat162float(w1h[k+1]) + __bfloat162float(w1l[k+1]);
            t0 = fmaf(x0, a0, fmaf(x1, a1, t0));
            t1 = fmaf(x0, c0, fmaf(x1, c1, t1));
        }
        __syncthreads();   // tail reads done before overlay overwrites xs
    }

    #pragma unroll
    for (int mb = 0; mb < 2; mb++)
        #pragma unroll
        for (int Jl = 0; Jl < 2; Jl++)
            #pragma unroll
            for (int j = 0; j < 4; j++) {
                const int c  = warp * 64 + Jl * 32 + j * 8 + 2 * (lane & 3);
                const int r0 = mb * 16 + (lane >> 2), r1 = r0 + 8;
                const float* a = acc + mb * 32 + Jl * 16 + j * 4;
                float b0v = __ldg(bias + c), b1v = __ldg(bias + c + 1);
                float y00 = a[0] + b0v, y01 = a[1] + b1v;
                float y10 = a[2] + b0v, y11 = a[3] + b1v;
                if (RELU) {
                    y00 = fmaxf(y00, 0.f); y01 = fmaxf(y01, 0.f);
                    y10 = fmaxf(y10, 0.f); y11 = fmaxf(y11, 0.f);
                }
                if (RES) {
                    y00 += rd2(sm, XS(r0, c, 0), XS(r0, c, 1), 0);
                    y01 += rd2(sm, XS(r0, c, 0), XS(r0, c, 1), 1);
                    y10 += rd2(sm, XS(r1, c, 0), XS(r1, c, 1), 0);
                    y11 += rd2(sm, XS(r1, c, 0), XS(r1, c, 1), 1);
                }
                if (TO_LP) {
                    float* lp = (float*)sm;
                    lp[r0 * NTRIL + c] = y00; lp[r0 * NTRIL + c + 1] = y01;
                    lp[r1 * NTRIL + c] = y10; lp[r1 * NTRIL + c + 1] = y11;
                } else {
                    uint32_t h, l;
                    split2(y00, y01, h, l);
                    *(uint32_t*)(sm + XS(r0, c, 0)) = h;
                    *(uint32_t*)(sm + XS(r0, c, 1)) = l;
                    split2(y10, y11, h, l);
                    *(uint32_t*)(sm + XS(r1, c, 0)) = h;
                    *(uint32_t*)(sm + XS(r1, c, 1)) = l;
                }
            }
    if (TO_LP) {
        float* lp = (float*)sm;
        lp[tr * NTRIL + 512 + tcc]     = t0 + __ldg(bias + 512 + tcc);
        lp[tr * NTRIL + 512 + tcc + 1] = t1 + __ldg(bias + 513 + tcc);
    }
    __syncthreads();
}

__global__ void __launch_bounds__(256, 2)
main_kernel(const float* __restrict__ q,
            const float* __restrict__ bin, const float* __restrict__ bh1,
            const float* __restrict__ bh2, const float* __restrict__ bout,
            const float* __restrict__ bo,  float* __restrict__ out)
{
    extern __shared__ char sm[];
    const uint32_t smb = smem_u32(sm);
    const int tid = threadIdx.x;
    const int row0 = blockIdx.x * 32;

    {   // stage q (32x32 fp32) into xs hi/lo
        int r = tid >> 3, kq = (tid & 7) * 4;
        float4 v = *(const float4*)(q + (size_t)(row0 + r) * QDIM + kq);
        uint32_t h, l;
        split2(v.x, v.y, h, l);
        *(uint32_t*)(sm + XS(r, kq, 0)) = h;
        *(uint32_t*)(sm + XS(r, kq, 1)) = l;
        split2(v.z, v.w, h, l);
        *(uint32_t*)(sm + XS(r, kq + 2, 0)) = h;
        *(uint32_t*)(sm + XS(r, kq + 2, 1)) = l;
    }
    __syncthreads();

    tc_layer<2,  true,  false, false>(sm, smb, g_Fi, bin);
    tc_layer<32, true,  true,  false>(sm, smb, g_F1, bh1);
    tc_layer<32, true,  true,  false>(sm, smb, g_F2, bh2);
    tc_layer<32, false, false, false>(sm, smb, g_Fu, bout);
    tc_layer<32, false, false, true >(sm, smb, g_Fo, bo);

    // M = L @ L^T from Lp smem overlay (verified fp32 path)
    const float* ps = (const float*)sm;
    for (int idx = tid; idx < 32 * QDIM * QDIM; idx += 256) {
        int r = idx >> 10, ij = idx & 1023, i = ij >> 5, j = ij & 31;
        const float* pr = ps + r * NTRIL;
        int mn = i < j ? i : j, mx = i < j ? j : i;
        int bi = 32 + (i * (i - 1)) / 2, bj = 32 + (j * (j - 1)) / 2;
        float sum = 0.f;
        for (int k = 0; k < mn; k++)
            sum = fmaf(pr[bi + k], pr[bj + k], sum);
        if (i == j) {
            float d = pr[i] + BIAS_F;
            sum = fmaf(d, d, sum);
        } else {
            float lml = pr[32 + (mx * (mx - 1)) / 2 + mn];
            sum = fmaf(lml, pr[mn] + BIAS_F, sum);
        }
        out[(size_t)(row0 + r) * 1024 + ij] = sum;
    }
}

// ---------------- prep: weights -> fragment layout (unchanged) ----------------
#define FI_U32   (2 * 16 * 4 * 32 * 4)
#define FL_U32   (32 * 16 * 4 * 32 * 4)
#define MAIN_U32 (FI_U32 + 4 * FL_U32)
#define TAIL_E   (16 * 512)

__global__ void prep_kernel(const float* __restrict__ Win, const float* __restrict__ Wh1,
                            const float* __restrict__ Wh2, const float* __restrict__ Wou,
                            const float* __restrict__ Wo)
{
    const int total = MAIN_U32 + TAIL_E;
    for (int e = blockIdx.x * blockDim.x + threadIdx.x; e < total;
         e += gridDim.x * blockDim.x) {
        if (e < MAIN_U32) {
            const float* W; uint32_t* dst; int t, ncols;
            if (e < FI_U32) { W = Win; dst = (uint32_t*)g_Fi; t = e; ncols = 512; }
            else {
                int le = e - FI_U32, ly = le / FL_U32;
                t = le - ly * FL_U32;
                ncols = (ly == 3) ? 528 : 512;
                W   = (ly == 0) ? Wh1 : (ly == 1) ? Wh2 : (ly == 2) ? Wou : Wo;
                dst = (uint32_t*)((ly == 0) ? g_F1 : (ly == 1) ? g_F2 :
                                  (ly == 2) ? g_Fu : g_Fo);
            }
            int c = t & 3, l = (t >> 2) & 31, g = (t >> 7) & 3;
            int J = (t >> 9) & 15, S = t >> 13;
            int jl  = (g & 1) * 2 + (c >> 1);
            int sel = g >> 1;
            int n   = J * 32 + jl * 8 + (l >> 2);
            int k0  = S * 16 + (c & 1) * 8 + 2 * (l & 3);
            float v0 = __ldg(W + (size_t)k0 * ncols + n);
            float v1 = __ldg(W + (size_t)(k0 + 1) * ncols + n);
            __nv_bfloat16 h0 = __float2bfloat16(v0), h1 = __float2bfloat16(v1);
            __nv_bfloat16 o0, o1;
            if (sel == 0) { o0 = h0; o1 = h1; }
            else {
                o0 = __float2bfloat16(v0 - __bfloat162float(h0));
                o1 = __float2bfloat16(v1 - __bfloat162float(h1));
            }
            __nv_bfloat162 p = __halves2bfloat162(o0, o1);
            dst[t] = *(uint32_t*)&p;
        } else {
            int t = e - MAIN_U32;
            int nt = t >> 9, k = t & 511;
            float v = __ldg(Wo + (size_t)k * 528 + 512 + nt);
            __nv_bfloat16 h = __float2bfloat16(v);
            g_Wt_h[nt * 512 + k] = h;
            g_Wt_l[nt * 512 + k] = __float2bfloat16(v - __bfloat162float(h));
        }
    }
}

extern "C" void kernel_launch(void* const* d_in, const int* in_sizes, int n_in,
                              void* d_out, int out_size)
{
    const float* q    = (const float*)d_in[0];
    const float* Win  = (const float*)d_in[1];
    const float* bin  = (const float*)d_in[2];
    const float* Wh1  = (const float*)d_in[3];
    const float* bh1  = (const float*)d_in[4];
    const float* Wh2  = (const float*)d_in[5];
    const float* bh2  = (const float*)d_in[6];
    const float* Wout = (const float*)d_in[7];
    const float* bout = (const float*)d_in[8];
    const float* Wo   = (const float*)d_in[9];
    const float* bo   = (const float*)d_in[10];
    float* out = (float*)d_out;

    const int B = in_sizes[0] / QDIM;   // 65536

    cudaFuncSetAttribute(main_kernel,
                         cudaFuncAttributeMaxDynamicSharedMemorySize, SMEM_BYTES);

    prep_kernel<<<148, 512>>>(Win, Wh1, Wh2, Wout, Wo);
    main_kernel<<<B / 32, 256, SMEM_BYTES>>>(q, bin, bh1, bh2, bout, bo, out);
}

// round 11
// speedup vs baseline: 3.2984x; 1.7626x over previous
#include <cuda_runtime.h>
#include <cuda_bf16.h>
#include <cstdint>

// CholeskyMMNet: mma.sync bf16 hi/lo split; B fragments pre-shuffled in gmem
// (direct LDG); A smem-resident; 32 rows/CTA, 256 thr, 2 CTAs/SM.
// R10: W_o cols 512..527 tail = split-K mini-MMA (was scalar; L1 hog).

#define QDIM 32
#define HDIM 512
#define NTRIL 528
#define BIAS_F 2.0f

// fragment-layout weights: uint4 index ((S*16 + J)*4 + g)*32 + lane
//   g0 = hi, n8 blocks {0,1}; g1 = hi {2,3}; g2 = lo {0,1}; g3 = lo {2,3}
__device__ uint4 g_Fi[2  * 16 * 4 * 32];
__device__ uint4 g_F1[32 * 16 * 4 * 32];
__device__ uint4 g_F2[32 * 16 * 4 * 32];
__device__ uint4 g_Fu[32 * 16 * 4 * 32];
__device__ uint4 g_Fo[32 * 16 * 4 * 32];   // W_o cols 0..511
__device__ uint4 g_Ft[32 * 4 * 32];        // W_o cols 512..527 (pad to 543), (S*4+g)*32+lane

// xs: [32 rows][2048B] = hi 1KB | lo 1KB per row, XOR-swizzled (0..64K)
// Lp overlay: [32][528] fp32 at byte 0 (after final epilogue)
// tail partials: [8 warps][32 rows][16 cols] fp32 at PART_OFF
#define XS(r,k,sel) ((r)*2048 + ((((sel)<<10) + ((k)<<1)) ^ (((r)&7)<<4)))
#define PART_OFF 67584
#define SMEM_BYTES (PART_OFF + 8 * 32 * 16 * 4)   // 83968

__device__ __forceinline__ uint32_t smem_u32(const void* p) {
    uint32_t a;
    asm("{ .reg .u64 t; cvta.to.shared.u64 t, %1; cvt.u32.u64 %0, t; }" : "=r"(a) : "l"(p));
    return a;
}

#define LDSM4(d, addr) \
    asm volatile("ldmatrix.sync.aligned.m8n8.x4.shared.b16 {%0,%1,%2,%3}, [%4];" \
        : "=r"((d)[0]),"=r"((d)[1]),"=r"((d)[2]),"=r"((d)[3]) : "r"(addr))

#define MMA16816(c, a, b0, b1) \
    asm volatile("mma.sync.aligned.m16n8k16.row.col.f32.bf16.bf16.f32 " \
        "{%0,%1,%2,%3}, {%4,%5,%6,%7}, {%8,%9}, {%0,%1,%2,%3};" \
        : "+f"((c)[0]),"+f"((c)[1]),"+f"((c)[2]),"+f"((c)[3]) \
        : "r"((a)[0]),"r"((a)[1]),"r"((a)[2]),"r"((a)[3]), "r"(b0),"r"(b1))

__device__ __forceinline__ void split2(float a, float b, uint32_t& h, uint32_t& l) {
    __nv_bfloat16 ha = __float2bfloat16(a), hb = __float2bfloat16(b);
    __nv_bfloat162 hp = __halves2bfloat162(ha, hb);
    __nv_bfloat162 lp = __halves2bfloat162(
        __float2bfloat16(a - __bfloat162float(ha)),
        __float2bfloat16(b - __bfloat162float(hb)));
    h = *(uint32_t*)&hp; l = *(uint32_t*)&lp;
}
__device__ __forceinline__ float rd2(const char* sm, int off0, int off1, int idx) {
    __nv_bfloat162 h = *(const __nv_bfloat162*)(sm + off0);
    __nv_bfloat162 l = *(const __nv_bfloat162*)(sm + off1);
    return idx ? (__bfloat162float(h.y) + __bfloat162float(l.y))
               : (__bfloat162float(h.x) + __bfloat162float(l.x));
}

__device__ __forceinline__ void ldB4(uint4* b, const uint4* __restrict__ gF,
                                     int S, int J, int lane) {
    const uint4* p = gF + ((size_t)(S * 16 + J) * 4) * 32 + lane;
    b[0] = __ldg(p);       b[1] = __ldg(p + 32);
    b[2] = __ldg(p + 64);  b[3] = __ldg(p + 96);
}

// 12 MMAs: hh (q0,q1), hl (q2,q3), lh (q0,q1)
__device__ __forceinline__ void mma12(float* A, const uint32_t ah[4], const uint32_t al[4],
                                      const uint4& q0, const uint4& q1,
                                      const uint4& q2, const uint4& q3) {
    MMA16816(A+0,  ah, q0.x, q0.y); MMA16816(A+4,  ah, q0.z, q0.w);
    MMA16816(A+8,  ah, q1.x, q1.y); MMA16816(A+12, ah, q1.z, q1.w);
    MMA16816(A+0,  ah, q2.x, q2.y); MMA16816(A+4,  ah, q2.z, q2.w);
    MMA16816(A+8,  ah, q3.x, q3.y); MMA16816(A+12, ah, q3.z, q3.w);
    MMA16816(A+0,  al, q0.x, q0.y); MMA16816(A+4,  al, q0.z, q0.w);
    MMA16816(A+8,  al, q1.x, q1.y); MMA16816(A+12, al, q1.z, q1.w);
}

// D[32][512] = X @ W^T; warp tile m32 x n64 (J blocks 2w, 2w+1)
template<int NS, bool RELU, bool RES, bool TO_LP>
__device__ void tc_layer(char* __restrict__ sm, uint32_t smb,
                         const uint4* __restrict__ gF,
                         const float* __restrict__ bias)
{
    const int tid = threadIdx.x, warp = tid >> 5, lane = tid & 31;
    float acc[64];
    #pragma unroll
    for (int i = 0; i < 64; i++) acc[i] = 0.f;

    uint4 bq[8];
    ldB4(bq,     gF, 0, 2 * warp,     lane);
    ldB4(bq + 4, gF, 0, 2 * warp + 1, lane);

    #pragma unroll 1
    for (int S = 0; S < NS; S++) {
        const int kk = S * 16 + ((lane >> 4) << 3);
        const int rb = lane & 15;
        uint32_t ah0[4], al0[4], ah1[4], al1[4];
        LDSM4(ah0, smb + XS(rb, kk, 0));
        LDSM4(al0, smb + XS(rb, kk, 1));
        mma12(acc +  0, ah0, al0, bq[0], bq[1], bq[2], bq[3]);
        LDSM4(ah1, smb + XS(16 + rb, kk, 0));
        LDSM4(al1, smb + XS(16 + rb, kk, 1));
        mma12(acc + 32, ah1, al1, bq[0], bq[1], bq[2], bq[3]);
        if (S + 1 < NS) ldB4(bq, gF, S + 1, 2 * warp, lane);
        mma12(acc + 16, ah0, al0, bq[4], bq[5], bq[6], bq[7]);
        mma12(acc + 48, ah1, al1, bq[4], bq[5], bq[6], bq[7]);
        if (S + 1 < NS) ldB4(bq + 4, gF, S + 1, 2 * warp + 1, lane);
    }
    __syncthreads();   // all mainloop ldsm reads of xs complete

    float tv0 = 0.f, tv1 = 0.f;
    int tr = 0, tcc = 0;
    if (TO_LP) {
        // ---- mini-GEMM: Lp cols 512..527, split-K (warp w -> k chunk 64w..64w+63)
        float at[16];
        #pragma unroll
        for (int i = 0; i < 16; i++) at[i] = 0.f;
        #pragma unroll
        for (int s4 = 0; s4 < 4; s4++) {
            const int S = warp * 4 + s4;
            const int kk = S * 16 + ((lane >> 4) << 3);
            const int rb = lane & 15;
            uint4 th = __ldg(g_Ft + (S * 4 + 0) * 32 + lane);   // hi j0,j1
            uint4 tl = __ldg(g_Ft + (S * 4 + 2) * 32 + lane);   // lo j0,j1
            uint32_t ah0[4], al0[4], ah1[4], al1[4];
            LDSM4(ah0, smb + XS(rb, kk, 0));
            LDSM4(al0, smb + XS(rb, kk, 1));
            LDSM4(ah1, smb + XS(16 + rb, kk, 0));
            LDSM4(al1, smb + XS(16 + rb, kk, 1));
            MMA16816(at+0,  ah0, th.x, th.y); MMA16816(at+4,  ah0, th.z, th.w);
            MMA16816(at+0,  ah0, tl.x, tl.y); MMA16816(at+4,  ah0, tl.z, tl.w);
            MMA16816(at+0,  al0, th.x, th.y); MMA16816(at+4,  al0, th.z, th.w);
            MMA16816(at+8,  ah1, th.x, th.y); MMA16816(at+12, ah1, th.z, th.w);
            MMA16816(at+8,  ah1, tl.x, tl.y); MMA16816(at+12, ah1, tl.z, tl.w);
            MMA16816(at+8,  al1, th.x, th.y); MMA16816(at+12, al1, th.z, th.w);
        }
        // write per-warp partial [32][16]
        float* part = (float*)(sm + PART_OFF) + warp * 32 * 16;
        #pragma unroll
        for (int mb = 0; mb < 2; mb++)
            #pragma unroll
            for (int j = 0; j < 2; j++) {
                const int r0 = mb * 16 + (lane >> 2), r1 = r0 + 8;
                const int c  = j * 8 + 2 * (lane & 3);
                const float* a = at + mb * 8 + j * 4;
                part[r0 * 16 + c] = a[0]; part[r0 * 16 + c + 1] = a[1];
                part[r1 * 16 + c] = a[2]; part[r1 * 16 + c + 1] = a[3];
            }
        __syncthreads();   // partials visible; all xs reads complete

        // reduce 8 partials: 256 threads -> 2 cols each of 32x16
        tr = tid >> 3; tcc = (tid & 7) * 2;
        const float* pb = (const float*)(sm + PART_OFF);
        #pragma unroll
        for (int w = 0; w < 8; w++) {
            tv0 += pb[w * 512 + tr * 16 + tcc];
            tv1 += pb[w * 512 + tr * 16 + tcc + 1];
        }
        tv0 += __ldg(bias + 512 + tcc);
        tv1 += __ldg(bias + 513 + tcc);
    }

    #pragma unroll
    for (int mb = 0; mb < 2; mb++)
        #pragma unroll
        for (int Jl = 0; Jl < 2; Jl++)
            #pragma unroll
            for (int j = 0; j < 4; j++) {
                const int c  = warp * 64 + Jl * 32 + j * 8 + 2 * (lane & 3);
                const int r0 = mb * 16 + (lane >> 2), r1 = r0 + 8;
                const float* a = acc + mb * 32 + Jl * 16 + j * 4;
                float b0v = __ldg(bias + c), b1v = __ldg(bias + c + 1);
                float y00 = a[0] + b0v, y01 = a[1] + b1v;
                float y10 = a[2] + b0v, y11 = a[3] + b1v;
                if (RELU) {
                    y00 = fmaxf(y00, 0.f); y01 = fmaxf(y01, 0.f);
                    y10 = fmaxf(y10, 0.f); y11 = fmaxf(y11, 0.f);
                }
                if (RES) {
                    y00 += rd2(sm, XS(r0, c, 0), XS(r0, c, 1), 0);
                    y01 += rd2(sm, XS(r0, c, 0), XS(r0, c, 1), 1);
                    y10 += rd2(sm, XS(r1, c, 0), XS(r1, c, 1), 0);
                    y11 += rd2(sm, XS(r1, c, 0), XS(r1, c, 1), 1);
                }
                if (TO_LP) {
                    float* lp = (float*)sm;
                    lp[r0 * NTRIL + c] = y00; lp[r0 * NTRIL + c + 1] = y01;
                    lp[r1 * NTRIL + c] = y10; lp[r1 * NTRIL + c + 1] = y11;
                } else {
                    uint32_t h, l;
                    split2(y00, y01, h, l);
                    *(uint32_t*)(sm + XS(r0, c, 0)) = h;
                    *(uint32_t*)(sm + XS(r0, c, 1)) = l;
                    split2(y10, y11, h, l);
                    *(uint32_t*)(sm + XS(r1, c, 0)) = h;
                    *(uint32_t*)(sm + XS(r1, c, 1)) = l;
                }
            }
    if (TO_LP) {
        float* lp = (float*)sm;
        lp[tr * NTRIL + 512 + tcc]     = tv0;
        lp[tr * NTRIL + 512 + tcc + 1] = tv1;
    }
    __syncthreads();
}

__global__ void __launch_bounds__(256, 2)
main_kernel(const float* __restrict__ q,
            const float* __restrict__ bin, const float* __restrict__ bh1,
            const float* __restrict__ bh2, const float* __restrict__ bout,
            const float* __restrict__ bo,  float* __restrict__ out)
{
    extern __shared__ char sm[];
    const uint32_t smb = smem_u32(sm);
    const int tid = threadIdx.x;
    const int row0 = blockIdx.x * 32;

    {   // stage q (32x32 fp32) into xs hi/lo
        int r = tid >> 3, kq = (tid & 7) * 4;
        float4 v = *(const float4*)(q + (size_t)(row0 + r) * QDIM + kq);
        uint32_t h, l;
        split2(v.x, v.y, h, l);
        *(uint32_t*)(sm + XS(r, kq, 0)) = h;
        *(uint32_t*)(sm + XS(r, kq, 1)) = l;
        split2(v.z, v.w, h, l);
        *(uint32_t*)(sm + XS(r, kq + 2, 0)) = h;
        *(uint32_t*)(sm + XS(r, kq + 2, 1)) = l;
    }
    __syncthreads();

    tc_layer<2,  true,  false, false>(sm, smb, g_Fi, bin);
    tc_layer<32, true,  true,  false>(sm, smb, g_F1, bh1);
    tc_layer<32, true,  true,  false>(sm, smb, g_F2, bh2);
    tc_layer<32, false, false, false>(sm, smb, g_Fu, bout);
    tc_layer<32, false, false, true >(sm, smb, g_Fo, bo);

    // M = L @ L^T from Lp smem overlay (verified fp32 path)
    const float* ps = (const float*)sm;
    for (int idx = tid; idx < 32 * QDIM * QDIM; idx += 256) {
        int r = idx >> 10, ij = idx & 1023, i = ij >> 5, j = ij & 31;
        const float* pr = ps + r * NTRIL;
        int mn = i < j ? i : j, mx = i < j ? j : i;
        int bi = 32 + (i * (i - 1)) / 2, bj = 32 + (j * (j - 1)) / 2;
        float sum = 0.f;
        for (int k = 0; k < mn; k++)
            sum = fmaf(pr[bi + k], pr[bj + k], sum);
        if (i == j) {
            float d = pr[i] + BIAS_F;
            sum = fmaf(d, d, sum);
        } else {
            float lml = pr[32 + (mx * (mx - 1)) / 2 + mn];
            sum = fmaf(lml, pr[mn] + BIAS_F, sum);
        }
        out[(size_t)(row0 + r) * 1024 + ij] = sum;
    }
}

// ---------------- prep: weights -> fragment layout ----------------
#define FI_U32   (2 * 16 * 4 * 32 * 4)
#define FL_U32   (32 * 16 * 4 * 32 * 4)
#define MAIN_U32 (FI_U32 + 4 * FL_U32)
#define FT_U32   (32 * 4 * 32 * 4)

__global__ void prep_kernel(const float* __restrict__ Win, const float* __restrict__ Wh1,
                            const float* __restrict__ Wh2, const float* __restrict__ Wou,
                            const float* __restrict__ Wo)
{
    const int total = MAIN_U32 + FT_U32;
    for (int e = blockIdx.x * blockDim.x + threadIdx.x; e < total;
         e += gridDim.x * blockDim.x) {
        if (e < MAIN_U32) {
            const float* W; uint32_t* dst; int t, ncols;
            if (e < FI_U32) { W = Win; dst = (uint32_t*)g_Fi; t = e; ncols = 512; }
            else {
                int le = e - FI_U32, ly = le / FL_U32;
                t = le - ly * FL_U32;
                ncols = (ly == 3) ? 528 : 512;
                W   = (ly == 0) ? Wh1 : (ly == 1) ? Wh2 : (ly == 2) ? Wou : Wo;
                dst = (uint32_t*)((ly == 0) ? g_F1 : (ly == 1) ? g_F2 :
                                  (ly == 2) ? g_Fu : g_Fo);
            }
            int c = t & 3, l = (t >> 2) & 31, g = (t >> 7) & 3;
            int J = (t >> 9) & 15, S = t >> 13;
            int jl  = (g & 1) * 2 + (c >> 1);
            int sel = g >> 1;
            int n   = J * 32 + jl * 8 + (l >> 2);
            int k0  = S * 16 + (c & 1) * 8 + 2 * (l & 3);
            float v0 = __ldg(W + (size_t)k0 * ncols + n);
            float v1 = __ldg(W + (size_t)(k0 + 1) * ncols + n);
            __nv_bfloat16 h0 = __float2bfloat16(v0), h1 = __float2bfloat16(v1);
            __nv_bfloat16 o0, o1;
            if (sel == 0) { o0 = h0; o1 = h1; }
            else {
                o0 = __float2bfloat16(v0 - __bfloat162float(h0));
                o1 = __float2bfloat16(v1 - __bfloat162float(h1));
            }
            __nv_bfloat162 p = __halves2bfloat162(o0, o1);
            dst[t] = *(uint32_t*)&p;
        } else {
            // tail fragments: W_o cols 512..527 (pad to 543 with zeros)
            int t = e - MAIN_U32;
            int c = t & 3, l = (t >> 2) & 31, g = (t >> 7) & 3;
            int S = t >> 9;                       // 0..31
            int jl  = (g & 1) * 2 + (c >> 1);
            int sel = g >> 1;
            int n   = 512 + jl * 8 + (l >> 2);
            int k0  = S * 16 + (c & 1) * 8 + 2 * (l & 3);
            float v0 = (n < NTRIL) ? __ldg(Wo + (size_t)k0 * NTRIL + n) : 0.f;
            float v1 = (n < NTRIL) ? __ldg(Wo + (size_t)(k0 + 1) * NTRIL + n) : 0.f;
            __nv_bfloat16 h0 = __float2bfloat16(v0), h1 = __float2bfloat16(v1);
            __nv_bfloat16 o0, o1;
            if (sel == 0) { o0 = h0; o1 = h1; }
            else {
                o0 = __float2bfloat16(v0 - __bfloat162float(h0));
                o1 = __float2bfloat16(v1 - __bfloat162float(h1));
            }
            __nv_bfloat162 p = __halves2bfloat162(o0, o1);
            ((uint32_t*)g_Ft)[t] = *(uint32_t*)&p;
        }
    }
}

extern "C" void kernel_launch(void* const* d_in, const int* in_sizes, int n_in,
                              void* d_out, int out_size)
{
    const float* q    = (const float*)d_in[0];
    const float* Win  = (const float*)d_in[1];
    const float* bin  = (const float*)d_in[2];
    const float* Wh1  = (const float*)d_in[3];
    const float* bh1  = (const float*)d_in[4];
    const float* Wh2  = (const float*)d_in[5];
    const float* bh2  = (const float*)d_in[6];
    const float* Wout = (const float*)d_in[7];
    const float* bout = (const float*)d_in[8];
    const float* Wo   = (const float*)d_in[9];
    const float* bo   = (const float*)d_in[10];
    float* out = (float*)d_out;

    const int B = in_sizes[0] / QDIM;   // 65536

    cudaFuncSetAttribute(main_kernel,
                         cudaFuncAttributeMaxDynamicSharedMemorySize, SMEM_BYTES);

    prep_kernel<<<148, 512>>>(Win, Wh1, Wh2, Wout, Wo);
    main_kernel<<<B / 32, 256, SMEM_BYTES>>>(q, bin, bh1, bh2, bout, bo, out);
}